// round 9
// baseline (speedup 1.0000x reference)
#include <cuda_runtime.h>
#include <cuda_bf16.h>
#include <cuda_fp16.h>
#include <math.h>
#include <stdint.h>

#define NB      2
#define LQ      8192
#define LEN_IN  149760
#define DM      256
#define NHEADS  8
#define NLEV    4
#define NPTS    4
#define DHEAD   32

// ---------------- scratch (device globals; no cudaMalloc allowed) ----------
__device__ __half g_value[(size_t)NB * LEN_IN * DM];                     // 153 MB
__device__ float  g_offattn[(size_t)NB * LQ * 512];                     // off 0..383, logits 384..511
__device__ float  g_mid  [(size_t)NB * LQ * DM];                        // 16 MB
__device__ __nv_bfloat16 g_wv_hi [DM * DM];
__device__ __nv_bfloat16 g_wv_lo [DM * DM];
__device__ __nv_bfloat16 g_wo_hi [DM * DM];
__device__ __nv_bfloat16 g_wo_lo [DM * DM];
__device__ __nv_bfloat16 g_wfa_hi[512 * DM];
__device__ __nv_bfloat16 g_wfa_lo[512 * DM];
__device__ float  g_bfa[512];

// ============================ PTX helpers ===================================
__device__ __forceinline__ uint32_t smem_u32(const void* p) {
    uint32_t a;
    asm("{ .reg .u64 t; cvta.to.shared.u64 t, %1; cvt.u32.u64 %0, t; }" : "=r"(a) : "l"(p));
    return a;
}
__device__ __forceinline__ void ldsm_x4(uint32_t* r, uint32_t addr) {
    asm volatile("ldmatrix.sync.aligned.m8n8.x4.shared.b16 {%0,%1,%2,%3}, [%4];"
        : "=r"(r[0]), "=r"(r[1]), "=r"(r[2]), "=r"(r[3]) : "r"(addr));
}
__device__ __forceinline__ void mma_bf16(float* d, const uint32_t* a,
                                         uint32_t b0, uint32_t b1) {
    asm volatile(
        "mma.sync.aligned.m16n8k16.row.col.f32.bf16.bf16.f32 "
        "{%0,%1,%2,%3}, {%4,%5,%6,%7}, {%8,%9}, {%0,%1,%2,%3};"
        : "+f"(d[0]), "+f"(d[1]), "+f"(d[2]), "+f"(d[3])
        : "r"(a[0]), "r"(a[1]), "r"(a[2]), "r"(a[3]), "r"(b0), "r"(b1));
}
#define CP_ASYNC16(dst, src) \
    asm volatile("cp.async.cg.shared.global [%0], [%1], 16;" :: "r"(dst), "l"(src))
#define CP_COMMIT() asm volatile("cp.async.commit_group;" ::: "memory")
#define CP_WAIT(n)  asm volatile("cp.async.wait_group %0;" :: "n"(n) : "memory")

__device__ __forceinline__ void cvt_split_store(char* smem, int offHi, int offLo,
                                                uint32_t eoff, float4 v) {
    __nv_bfloat162 h01 = __floats2bfloat162_rn(v.x, v.y);
    __nv_bfloat162 h23 = __floats2bfloat162_rn(v.z, v.w);
    float lx = v.x - __bfloat162float(__low2bfloat16(h01));
    float ly = v.y - __bfloat162float(__high2bfloat16(h01));
    float lz = v.z - __bfloat162float(__low2bfloat16(h23));
    float lw = v.w - __bfloat162float(__high2bfloat16(h23));
    __nv_bfloat162 l01 = __floats2bfloat162_rn(lx, ly);
    __nv_bfloat162 l23 = __floats2bfloat162_rn(lz, lw);
    *(uint2*)(smem + offHi + eoff) = make_uint2(*(uint32_t*)&h01, *(uint32_t*)&h23);
    *(uint2*)(smem + offLo + eoff) = make_uint2(*(uint32_t*)&l01, *(uint32_t*)&l23);
}

#define SA        72

// ---------------- generic 128x128-tile mma GEMM (fused off+attn) -----------
#define OFF_AHI   0
#define OFF_ALO   18432
#define OFF_BHI   36864
#define OFF_BLO   55296
#define SMEM_MMA  73728

__global__ __launch_bounds__(256, 1) void mma_gemm_kernel(
    const float* __restrict__ A,
    const __nv_bfloat16* __restrict__ Bt_hi,
    const __nv_bfloat16* __restrict__ Bt_lo,
    const float* __restrict__ bias,
    float* __restrict__ C, int Nc)
{
    extern __shared__ char smem[];
    const uint32_t sb = smem_u32(smem);
    const int tid   = threadIdx.x;
    const int lane  = tid & 31;
    const int wid   = tid >> 5;
    const int mwarp = wid & 1;
    const int nwarp = wid >> 1;
    const int bn    = blockIdx.x;
    const size_t rowBase = (size_t)blockIdx.y * 128;

    float acc[4][4][4];
#pragma unroll
    for (int i = 0; i < 4; i++)
#pragma unroll
        for (int j = 0; j < 4; j++)
#pragma unroll
            for (int r = 0; r < 4; r++) acc[i][j][r] = 0.f;

    const int a_row = lane & 15, a_kh = lane >> 4;
    const uint32_t aAddrHi = sb + OFF_AHI +
        (uint32_t)(((mwarp * 64 + a_row) * SA + a_kh * 8) * 2);
    const int b_g = lane >> 3, b_r = lane & 7;
    const uint32_t bAddrHi = sb + OFF_BHI +
        (uint32_t)(((nwarp * 32 + (b_g >> 1) * 8 + b_r) * SA + (b_g & 1) * 8) * 2);

#pragma unroll 1
    for (int ch = 0; ch < 4; ch++) {
        const int k0 = ch * 64;
#pragma unroll
        for (int it = 0; it < 8; it++) {
            int idx = tid + it * 256;
            int row = idx >> 4, q = idx & 15;
            float4 v = *(const float4*)(A + (rowBase + row) * 256 + k0 + q * 4);
            cvt_split_store(smem, OFF_AHI, OFF_ALO,
                            (uint32_t)((row * SA + q * 4) * 2), v);
        }
#pragma unroll
        for (int it = 0; it < 4; it++) {
            int idx = tid + it * 256;
            int n = idx >> 3, q = idx & 7;
            uint32_t eoff = (uint32_t)((n * SA + q * 8) * 2);
            size_t goff = (size_t)(bn * 128 + n) * 256 + k0 + q * 8;
            *(uint4*)(smem + OFF_BHI + eoff) = *(const uint4*)(Bt_hi + goff);
            *(uint4*)(smem + OFF_BLO + eoff) = *(const uint4*)(Bt_lo + goff);
        }
        __syncthreads();

#pragma unroll
        for (int ks = 0; ks < 4; ks++) {
            const uint32_t kb = (uint32_t)(ks * 32);
            uint32_t ah[4][4], al[4][4];
#pragma unroll
            for (int mt = 0; mt < 4; mt++) {
                uint32_t ad = aAddrHi + (uint32_t)(mt * 16 * SA * 2) + kb;
                ldsm_x4(ah[mt], ad);
                ldsm_x4(al[mt], ad + (OFF_ALO - OFF_AHI));
            }
            uint32_t bh[2][4], bl[2][4];
#pragma unroll
            for (int pr = 0; pr < 2; pr++) {
                uint32_t bd = bAddrHi + (uint32_t)(pr * 16 * SA * 2) + kb;
                ldsm_x4(bh[pr], bd);
                ldsm_x4(bl[pr], bd + (OFF_BLO - OFF_BHI));
            }
#pragma unroll
            for (int mt = 0; mt < 4; mt++)
#pragma unroll
                for (int nt = 0; nt < 4; nt++) {
                    const int pr = nt >> 1, h = (nt & 1) * 2;
                    mma_bf16(acc[mt][nt], ah[mt], bh[pr][h], bh[pr][h + 1]);
                    mma_bf16(acc[mt][nt], ah[mt], bl[pr][h], bl[pr][h + 1]);
                    mma_bf16(acc[mt][nt], al[mt], bh[pr][h], bh[pr][h + 1]);
                }
        }
        __syncthreads();
    }

#pragma unroll
    for (int nt = 0; nt < 4; nt++) {
        const int col = bn * 128 + nwarp * 32 + nt * 8 + (lane & 3) * 2;
        const float2 bb = *(const float2*)(bias + col);
#pragma unroll
        for (int mt = 0; mt < 4; mt++) {
            const size_t row0 = rowBase + mwarp * 64 + mt * 16 + (lane >> 2);
            float2 o0, o1;
            o0.x = acc[mt][nt][0] + bb.x; o0.y = acc[mt][nt][1] + bb.y;
            o1.x = acc[mt][nt][2] + bb.x; o1.y = acc[mt][nt][3] + bb.y;
            *(float2*)(C + row0 * Nc + col)       = o0;
            *(float2*)(C + (row0 + 8) * Nc + col) = o1;
        }
    }
}

// ------- pipelined 128x256-tile mma GEMM, templated output type ------------
#define V_AHI     0
#define V_ALO     18432
#define V_B0      36864
#define V_BSTRIDE 73728
#define SMEM_V    184320

template <bool HALF_OUT>
__global__ __launch_bounds__(256, 1) void mma_gemm256_kernel(
    const float* __restrict__ A,
    const __nv_bfloat16* __restrict__ Bt_hi,
    const __nv_bfloat16* __restrict__ Bt_lo,
    const float* __restrict__ bias,
    void* __restrict__ Cout)
{
    extern __shared__ char smem[];
    const uint32_t sb = smem_u32(smem);
    const int tid   = threadIdx.x;
    const int lane  = tid & 31;
    const int wid   = tid >> 5;
    const int mwarp = wid & 1;
    const int nwarp = wid >> 1;
    const size_t rowBase = (size_t)blockIdx.x * 128;

    float acc[4][8][4];
#pragma unroll
    for (int i = 0; i < 4; i++)
#pragma unroll
        for (int j = 0; j < 8; j++)
#pragma unroll
            for (int r = 0; r < 4; r++) acc[i][j][r] = 0.f;

    const int a_row = lane & 15, a_kh = lane >> 4;
    const uint32_t aAddrHi = sb + V_AHI +
        (uint32_t)(((mwarp * 64 + a_row) * SA + a_kh * 8) * 2);
    const int b_g = lane >> 3, b_r = lane & 7;
    const uint32_t bAddrBase = sb + V_B0 +
        (uint32_t)(((nwarp * 64 + (b_g >> 1) * 8 + b_r) * SA + (b_g & 1) * 8) * 2);

    float4 apre[8];
#pragma unroll
    for (int it = 0; it < 8; it++) {
        int idx = tid + it * 256;
        int row = idx >> 4, q = idx & 15;
        apre[it] = *(const float4*)(A + (rowBase + row) * 256 + 0 + q * 4);
    }
#pragma unroll
    for (int it = 0; it < 8; it++) {
        int idx = tid + it * 256;
        int n = idx >> 3, q = idx & 7;
        uint32_t eoff = (uint32_t)((n * SA + q * 8) * 2);
        CP_ASYNC16(sb + V_B0 + eoff, Bt_hi + (size_t)n * 256 + q * 8);
        CP_ASYNC16(sb + V_B0 + 36864 + eoff, Bt_lo + (size_t)n * 256 + q * 8);
    }
    CP_COMMIT();

#pragma unroll 1
    for (int ch = 0; ch < 4; ch++) {
        const int buf = ch & 1;
#pragma unroll
        for (int it = 0; it < 8; it++) {
            int idx = tid + it * 256;
            int row = idx >> 4, q = idx & 15;
            cvt_split_store(smem, V_AHI, V_ALO,
                            (uint32_t)((row * SA + q * 4) * 2), apre[it]);
        }
        if (ch < 3) {
            const int k1 = (ch + 1) * 64;
            const uint32_t bsm = sb + V_B0 + (uint32_t)((buf ^ 1) * V_BSTRIDE);
#pragma unroll
            for (int it = 0; it < 8; it++) {
                int idx = tid + it * 256;
                int n = idx >> 3, q = idx & 7;
                uint32_t eoff = (uint32_t)((n * SA + q * 8) * 2);
                CP_ASYNC16(bsm + eoff,         Bt_hi + (size_t)n * 256 + k1 + q * 8);
                CP_ASYNC16(bsm + 36864 + eoff, Bt_lo + (size_t)n * 256 + k1 + q * 8);
            }
            CP_COMMIT();
            CP_WAIT(1);
        } else {
            CP_WAIT(0);
        }
        __syncthreads();

        if (ch < 3) {
            const int k1 = (ch + 1) * 64;
#pragma unroll
            for (int it = 0; it < 8; it++) {
                int idx = tid + it * 256;
                int row = idx >> 4, q = idx & 15;
                apre[it] = *(const float4*)(A + (rowBase + row) * 256 + k1 + q * 4);
            }
        }

        const uint32_t bAddrHi = bAddrBase + (uint32_t)(buf * V_BSTRIDE);
#pragma unroll
        for (int ks = 0; ks < 4; ks++) {
            const uint32_t kb = (uint32_t)(ks * 32);
            uint32_t ah[4][4], al[4][4];
#pragma unroll
            for (int mt = 0; mt < 4; mt++) {
                uint32_t ad = aAddrHi + (uint32_t)(mt * 16 * SA * 2) + kb;
                ldsm_x4(ah[mt], ad);
                ldsm_x4(al[mt], ad + (V_ALO - V_AHI));
            }
#pragma unroll
            for (int pr = 0; pr < 4; pr++) {
                uint32_t bh[4], bl[4];
                uint32_t bd = bAddrHi + (uint32_t)(pr * 16 * SA * 2) + kb;
                ldsm_x4(bh, bd);
                ldsm_x4(bl, bd + 36864);
#pragma unroll
                for (int h2 = 0; h2 < 2; h2++) {
                    const int nt = pr * 2 + h2, h = h2 * 2;
#pragma unroll
                    for (int mt = 0; mt < 4; mt++) {
                        mma_bf16(acc[mt][nt], ah[mt], bh[h], bh[h + 1]);
                        mma_bf16(acc[mt][nt], ah[mt], bl[h], bl[h + 1]);
                        mma_bf16(acc[mt][nt], al[mt], bh[h], bh[h + 1]);
                    }
                }
            }
        }
        __syncthreads();
    }

#pragma unroll
    for (int nt = 0; nt < 8; nt++) {
        const int col = nwarp * 64 + nt * 8 + (lane & 3) * 2;
        const float2 bb = *(const float2*)(bias + col);
#pragma unroll
        for (int mt = 0; mt < 4; mt++) {
            const size_t row0 = rowBase + mwarp * 64 + mt * 16 + (lane >> 2);
            if (HALF_OUT) {
                __half* Ch = (__half*)Cout;
                __half2 h0 = __floats2half2_rn(acc[mt][nt][0] + bb.x,
                                               acc[mt][nt][1] + bb.y);
                __half2 h1 = __floats2half2_rn(acc[mt][nt][2] + bb.x,
                                               acc[mt][nt][3] + bb.y);
                *(__half2*)(Ch + row0 * 256 + col)       = h0;
                *(__half2*)(Ch + (row0 + 8) * 256 + col) = h1;
            } else {
                float* Cf = (float*)Cout;
                float2 o0, o1;
                o0.x = acc[mt][nt][0] + bb.x; o0.y = acc[mt][nt][1] + bb.y;
                o1.x = acc[mt][nt][2] + bb.x; o1.y = acc[mt][nt][3] + bb.y;
                *(float2*)(Cf + row0 * 256 + col)       = o0;
                *(float2*)(Cf + (row0 + 8) * 256 + col) = o1;
            }
        }
    }
}

// ---- unified prep: transposed bf16 splits of all 4 weights + fused bias ----
__global__ void prep_all_kernel(const float* __restrict__ Wv,
                                const float* __restrict__ Wout,
                                const float* __restrict__ Woff,
                                const float* __restrict__ Wattn,
                                const float* __restrict__ boff,
                                const float* __restrict__ battn)
{
    int idx = blockIdx.x * 256 + threadIdx.x;
    int row = idx >> 8, k = idx & 255;
    float v;
    __nv_bfloat16 *dh, *dl;
    int n;
    if (row < 256)      { n = row;       v = Wv  [k * 256 + n]; dh = g_wv_hi;  dl = g_wv_lo;  }
    else if (row < 512) { n = row - 256; v = Wout[k * 256 + n]; dh = g_wo_hi;  dl = g_wo_lo;  }
    else if (row < 896) { n = row - 512; v = Woff[k * 384 + n]; dh = g_wfa_hi; dl = g_wfa_lo; }
    else                { n = row - 896 + 384;
                          v = Wattn[k * 128 + (row - 896)];     dh = g_wfa_hi; dl = g_wfa_lo; }
    __nv_bfloat16 h = __float2bfloat16(v);
    dh[n * 256 + k] = h;
    dl[n * 256 + k] = __float2bfloat16(v - __bfloat162float(h));

    if (blockIdx.x < 2) {
        int t = blockIdx.x * 256 + threadIdx.x;
        g_bfa[t] = (t < 384) ? boff[t] : battn[t - 384];
    }
}

// ====== fused softmax + trilinear deformable sampling (fp16 value) =========
// Phase 1: cooperative addr gen -> (idx, a*w) pairs staged in smem (128/head).
// Phase 2: half-warps process even/odd corners; each lane loads a __half2
//          (2 channels) -> 64 LDGs/warp instead of 128, no inner-loop shfl.
__global__ __launch_bounds__(256) void sample_kernel(
    const float* __restrict__ rp,
    const int*   __restrict__ shapes,
    const int*   __restrict__ starts)
{
    const int q    = blockIdx.x;
    const int h    = threadIdx.x >> 5;
    const int lane = threadIdx.x & 31;

    __shared__ float s_rp[NLEV * 3];
    __shared__ int   s_dim[NLEV * 3];
    __shared__ int   s_start[NLEV];
    __shared__ int   s_idx[NHEADS][128];
    __shared__ float s_aw [NHEADS][128];
    if (threadIdx.x < NLEV * 3) {
        s_rp[threadIdx.x]  = rp[(size_t)q * (NLEV * 3) + threadIdx.x];
        s_dim[threadIdx.x] = shapes[threadIdx.x];
    }
    if (threadIdx.x < NLEV) s_start[threadIdx.x] = starts[threadIdx.x];
    __syncthreads();

    const int n = q / LQ;
    const int o     = lane & 15;        // point 0..15
    const int chalf = lane >> 4;        // corner half
    const int l     = o >> 2;

    // softmax over 16 logits (width-16 shuffle reduction)
    float logit = g_offattn[(size_t)q * 512 + 384 + h * 16 + o];
    float m = logit;
#pragma unroll
    for (int s = 8; s > 0; s >>= 1)
        m = fmaxf(m, __shfl_xor_sync(0xffffffffu, m, s, 16));
    float e = __expf(logit - m);
    float ssum = e;
#pragma unroll
    for (int s = 8; s > 0; s >>= 1)
        ssum += __shfl_xor_sync(0xffffffffu, ssum, s, 16);
    const float a = e / ssum;

    const float* offq = g_offattn + (size_t)q * 512 + h * 48 + o * 3;
    const int D = s_dim[l * 3 + 0];
    const int H = s_dim[l * 3 + 1];
    const int W = s_dim[l * 3 + 2];
    const float x = (s_rp[l * 3 + 0] + offq[0] / (float)W) * (float)W - 0.5f;
    const float y = (s_rp[l * 3 + 1] + offq[1] / (float)H) * (float)H - 0.5f;
    const float z = (s_rp[l * 3 + 2] + offq[2] / (float)D) * (float)D - 0.5f;
    const float x0f = floorf(x), y0f = floorf(y), z0f = floorf(z);
    const int   x0 = (int)x0f,   y0 = (int)y0f,   z0 = (int)z0f;
    const float fx = x - x0f,    fy = y - y0f,    fz = z - z0f;

#pragma unroll
    for (int cc = 0; cc < 4; cc++) {
        const int c  = chalf * 4 + cc;
        const int dx = c & 1, dy = (c >> 1) & 1, dz = (c >> 2) & 1;
        const int xi = x0 + dx, yi = y0 + dy, zi = z0 + dz;
        const float w = (dx ? fx : 1.f - fx)
                      * (dy ? fy : 1.f - fy)
                      * (dz ? fz : 1.f - fz);
        const bool valid = (xi >= 0) & (xi < W) & (yi >= 0) & (yi < H) &
                           (zi >= 0) & (zi < D) & (w != 0.f);
        s_idx[h][o * 8 + c] = valid ? ((zi * H + yi) * W + xi) : -1;
        s_aw [h][o * 8 + c] = a * w;
    }
    __syncwarp();

    // ---- phase 2: gather, 2 corners per iteration across half-warps ----
    const int half = lane >> 4;          // which corner parity this lane handles
    const int ch2  = lane & 15;          // channel-pair 0..15 (channels 2*ch2, 2*ch2+1)
    const __half* vb[NLEV];
#pragma unroll
    for (int lv = 0; lv < NLEV; lv++)
        vb[lv] = g_value + ((size_t)(n * LEN_IN + s_start[lv])) * DM
               + h * DHEAD + ch2 * 2;

    float ax = 0.f, ay = 0.f;
#pragma unroll 16
    for (int i = 0; i < 64; i++) {
        const int cg  = 2 * i + half;    // global corner 0..127 (point*8+corner)
        const int lv  = cg >> 5;         // = (point)>>2
        const int idx = s_idx[h][cg];
        const float aw = s_aw[h][cg];
        if (idx >= 0) {
            __half2 v2 = __ldg((const __half2*)(vb[lv] + (size_t)idx * DM));
            float2 vf = __half22float2(v2);
            ax = fmaf(aw, vf.x, ax);
            ay = fmaf(aw, vf.y, ay);
        }
    }
    // recombine even/odd corner halves
    ax += __shfl_xor_sync(0xffffffffu, ax, 16);
    ay += __shfl_xor_sync(0xffffffffu, ay, 16);
    if (lane < 16)
        *(float2*)(g_mid + (size_t)q * DM + h * DHEAD + ch2 * 2) =
            make_float2(ax, ay);
}

// ---------------------------------------------------------------------------
extern "C" void kernel_launch(void* const* d_in, const int* in_sizes, int n_in,
                              void* d_out, int out_size)
{
    const float* query  = (const float*)d_in[0];
    const float* refp   = (const float*)d_in[1];
    const float* inp    = (const float*)d_in[2];
    const int*   shapes = (const int*)  d_in[3];
    const int*   starts = (const int*)  d_in[4];
    const float* Wv     = (const float*)d_in[5];
    const float* bv     = (const float*)d_in[6];
    const float* Woff   = (const float*)d_in[7];
    const float* boff   = (const float*)d_in[8];
    const float* Wattn  = (const float*)d_in[9];
    const float* battn  = (const float*)d_in[10];
    const float* Wout   = (const float*)d_in[11];
    const float* bout   = (const float*)d_in[12];
    float* out = (float*)d_out;

    __half* pv;  float *poa, *pm, *pbfa;
    __nv_bfloat16 *pwvh, *pwvl, *pwoh, *pwol, *pwfah, *pwfal;
    cudaGetSymbolAddress((void**)&pv,  g_value);
    cudaGetSymbolAddress((void**)&poa, g_offattn);
    cudaGetSymbolAddress((void**)&pm,  g_mid);
    cudaGetSymbolAddress((void**)&pbfa, g_bfa);
    cudaGetSymbolAddress((void**)&pwvh, g_wv_hi);
    cudaGetSymbolAddress((void**)&pwvl, g_wv_lo);
    cudaGetSymbolAddress((void**)&pwoh, g_wo_hi);
    cudaGetSymbolAddress((void**)&pwol, g_wo_lo);
    cudaGetSymbolAddress((void**)&pwfah, g_wfa_hi);
    cudaGetSymbolAddress((void**)&pwfal, g_wfa_lo);

    cudaFuncSetAttribute(mma_gemm_kernel,
                         cudaFuncAttributeMaxDynamicSharedMemorySize, SMEM_MMA);
    cudaFuncSetAttribute(mma_gemm256_kernel<true>,
                         cudaFuncAttributeMaxDynamicSharedMemorySize, SMEM_V);
    cudaFuncSetAttribute(mma_gemm256_kernel<false>,
                         cudaFuncAttributeMaxDynamicSharedMemorySize, SMEM_V);

    // 0) prep all transposed bf16 splits + fused bias (one launch)
    prep_all_kernel<<<1024, 256>>>(Wv, Wout, Woff, Wattn, boff, battn);

    // 1) value = input_flatten @ Wv + bv -> fp16  (pipelined 128x256 tile)
    mma_gemm256_kernel<true><<<(NB * LEN_IN) / 128, 256, SMEM_V>>>(
        inp, pwvh, pwvl, bv, pv);

    // 2) [off|attn logits] = query @ [Woff|Wattn] + [boff|battn]  (N=512)
    {
        dim3 grid(4, (NB * LQ) / 128);
        mma_gemm_kernel<<<grid, 256, SMEM_MMA>>>(query, pwfah, pwfal, pbfa, poa, 512);
    }
    // 3) fused softmax + deformable trilinear sampling -> g_mid
    sample_kernel<<<NB * LQ, 256>>>(refp, shapes, starts);

    // 4) out = g_mid @ Wout + bout          (pipelined 128x256 tile, fp32)
    mma_gemm256_kernel<false><<<(NB * LQ) / 128, 256, SMEM_V>>>(
        pm, pwoh, pwol, bout, out);
}

// round 11
// speedup vs baseline: 1.1612x; 1.1612x over previous
#include <cuda_runtime.h>
#include <cuda_bf16.h>
#include <cuda_fp16.h>
#include <math.h>
#include <stdint.h>

#define NB      2
#define LQ      8192
#define LEN_IN  149760
#define DM      256
#define NHEADS  8
#define NLEV    4
#define NPTS    4
#define DHEAD   32
#define NVBLK   ((NB * LEN_IN) / 128)   // 2340 value-GEMM blocks

// ---------------- scratch (device globals; no cudaMalloc allowed) ----------
__device__ __half g_value[(size_t)NB * LEN_IN * DM];                     // 153 MB
__device__ float  g_offattn[(size_t)NB * LQ * 512];                     // off 0..383, logits 384..511
__device__ float  g_mid  [(size_t)NB * LQ * DM];                        // 16 MB
__device__ __nv_bfloat16 g_wv_hi [DM * DM];
__device__ __nv_bfloat16 g_wv_lo [DM * DM];
__device__ __nv_bfloat16 g_wo_hi [DM * DM];
__device__ __nv_bfloat16 g_wo_lo [DM * DM];
__device__ __nv_bfloat16 g_wfa_hi[512 * DM];
__device__ __nv_bfloat16 g_wfa_lo[512 * DM];
__device__ float  g_bfa[512];

// ============================ PTX helpers ===================================
__device__ __forceinline__ uint32_t smem_u32(const void* p) {
    uint32_t a;
    asm("{ .reg .u64 t; cvta.to.shared.u64 t, %1; cvt.u32.u64 %0, t; }" : "=r"(a) : "l"(p));
    return a;
}
__device__ __forceinline__ void ldsm_x4(uint32_t* r, uint32_t addr) {
    asm volatile("ldmatrix.sync.aligned.m8n8.x4.shared.b16 {%0,%1,%2,%3}, [%4];"
        : "=r"(r[0]), "=r"(r[1]), "=r"(r[2]), "=r"(r[3]) : "r"(addr));
}
__device__ __forceinline__ void mma_bf16(float* d, const uint32_t* a,
                                         uint32_t b0, uint32_t b1) {
    asm volatile(
        "mma.sync.aligned.m16n8k16.row.col.f32.bf16.bf16.f32 "
        "{%0,%1,%2,%3}, {%4,%5,%6,%7}, {%8,%9}, {%0,%1,%2,%3};"
        : "+f"(d[0]), "+f"(d[1]), "+f"(d[2]), "+f"(d[3])
        : "r"(a[0]), "r"(a[1]), "r"(a[2]), "r"(a[3]), "r"(b0), "r"(b1));
}
#define CP_ASYNC16(dst, src) \
    asm volatile("cp.async.cg.shared.global [%0], [%1], 16;" :: "r"(dst), "l"(src))
#define CP_COMMIT() asm volatile("cp.async.commit_group;" ::: "memory")
#define CP_WAIT(n)  asm volatile("cp.async.wait_group %0;" :: "n"(n) : "memory")

__device__ __forceinline__ void cvt_split_store(char* smem, int offHi, int offLo,
                                                uint32_t eoff, float4 v) {
    __nv_bfloat162 h01 = __floats2bfloat162_rn(v.x, v.y);
    __nv_bfloat162 h23 = __floats2bfloat162_rn(v.z, v.w);
    float lx = v.x - __bfloat162float(__low2bfloat16(h01));
    float ly = v.y - __bfloat162float(__high2bfloat16(h01));
    float lz = v.z - __bfloat162float(__low2bfloat16(h23));
    float lw = v.w - __bfloat162float(__high2bfloat16(h23));
    __nv_bfloat162 l01 = __floats2bfloat162_rn(lx, ly);
    __nv_bfloat162 l23 = __floats2bfloat162_rn(lz, lw);
    *(uint2*)(smem + offHi + eoff) = make_uint2(*(uint32_t*)&h01, *(uint32_t*)&h23);
    *(uint2*)(smem + offLo + eoff) = make_uint2(*(uint32_t*)&l01, *(uint32_t*)&l23);
}

#define SA        72

// ---------------- 128x128-tile GEMM body (off/attn) ------------------------
#define OFF_AHI   0
#define OFF_ALO   18432
#define OFF_BHI   36864
#define OFF_BLO   55296

__device__ __forceinline__ void gemm128_body(
    char* smem, int bn, int bm,
    const float* __restrict__ A,
    const __nv_bfloat16* __restrict__ Bt_hi,
    const __nv_bfloat16* __restrict__ Bt_lo,
    const float* __restrict__ bias,
    float* __restrict__ C, int Nc)
{
    const uint32_t sb = smem_u32(smem);
    const int tid   = threadIdx.x;
    const int lane  = tid & 31;
    const int wid   = tid >> 5;
    const int mwarp = wid & 1;
    const int nwarp = wid >> 1;
    const size_t rowBase = (size_t)bm * 128;

    float acc[4][4][4];
#pragma unroll
    for (int i = 0; i < 4; i++)
#pragma unroll
        for (int j = 0; j < 4; j++)
#pragma unroll
            for (int r = 0; r < 4; r++) acc[i][j][r] = 0.f;

    const int a_row = lane & 15, a_kh = lane >> 4;
    const uint32_t aAddrHi = sb + OFF_AHI +
        (uint32_t)(((mwarp * 64 + a_row) * SA + a_kh * 8) * 2);
    const int b_g = lane >> 3, b_r = lane & 7;
    const uint32_t bAddrHi = sb + OFF_BHI +
        (uint32_t)(((nwarp * 32 + (b_g >> 1) * 8 + b_r) * SA + (b_g & 1) * 8) * 2);

#pragma unroll 1
    for (int ch = 0; ch < 4; ch++) {
        const int k0 = ch * 64;
#pragma unroll
        for (int it = 0; it < 8; it++) {
            int idx = tid + it * 256;
            int row = idx >> 4, q = idx & 15;
            float4 v = *(const float4*)(A + (rowBase + row) * 256 + k0 + q * 4);
            cvt_split_store(smem, OFF_AHI, OFF_ALO,
                            (uint32_t)((row * SA + q * 4) * 2), v);
        }
#pragma unroll
        for (int it = 0; it < 4; it++) {
            int idx = tid + it * 256;
            int n = idx >> 3, q = idx & 7;
            uint32_t eoff = (uint32_t)((n * SA + q * 8) * 2);
            size_t goff = (size_t)(bn * 128 + n) * 256 + k0 + q * 8;
            *(uint4*)(smem + OFF_BHI + eoff) = *(const uint4*)(Bt_hi + goff);
            *(uint4*)(smem + OFF_BLO + eoff) = *(const uint4*)(Bt_lo + goff);
        }
        __syncthreads();

#pragma unroll
        for (int ks = 0; ks < 4; ks++) {
            const uint32_t kb = (uint32_t)(ks * 32);
            uint32_t ah[4][4], al[4][4];
#pragma unroll
            for (int mt = 0; mt < 4; mt++) {
                uint32_t ad = aAddrHi + (uint32_t)(mt * 16 * SA * 2) + kb;
                ldsm_x4(ah[mt], ad);
                ldsm_x4(al[mt], ad + (OFF_ALO - OFF_AHI));
            }
            uint32_t bh[2][4], bl[2][4];
#pragma unroll
            for (int pr = 0; pr < 2; pr++) {
                uint32_t bd = bAddrHi + (uint32_t)(pr * 16 * SA * 2) + kb;
                ldsm_x4(bh[pr], bd);
                ldsm_x4(bl[pr], bd + (OFF_BLO - OFF_BHI));
            }
#pragma unroll
            for (int mt = 0; mt < 4; mt++)
#pragma unroll
                for (int nt = 0; nt < 4; nt++) {
                    const int pr = nt >> 1, h = (nt & 1) * 2;
                    mma_bf16(acc[mt][nt], ah[mt], bh[pr][h], bh[pr][h + 1]);
                    mma_bf16(acc[mt][nt], ah[mt], bl[pr][h], bl[pr][h + 1]);
                    mma_bf16(acc[mt][nt], al[mt], bh[pr][h], bh[pr][h + 1]);
                }
        }
        __syncthreads();
    }

#pragma unroll
    for (int nt = 0; nt < 4; nt++) {
        const int col = bn * 128 + nwarp * 32 + nt * 8 + (lane & 3) * 2;
        const float2 bb = *(const float2*)(bias + col);
#pragma unroll
        for (int mt = 0; mt < 4; mt++) {
            const size_t row0 = rowBase + mwarp * 64 + mt * 16 + (lane >> 2);
            float2 o0, o1;
            o0.x = acc[mt][nt][0] + bb.x; o0.y = acc[mt][nt][1] + bb.y;
            o1.x = acc[mt][nt][2] + bb.x; o1.y = acc[mt][nt][3] + bb.y;
            *(float2*)(C + row0 * Nc + col)       = o0;
            *(float2*)(C + (row0 + 8) * Nc + col) = o1;
        }
    }
}

// ------- pipelined 128x256-tile GEMM body -----------------------------------
#define V_AHI     0
#define V_ALO     18432
#define V_B0      36864
#define V_BSTRIDE 73728
#define SMEM_V    184320

template <bool HALF_OUT>
__device__ __forceinline__ void gemm256_body(
    char* smem, int bx,
    const float* __restrict__ A,
    const __nv_bfloat16* __restrict__ Bt_hi,
    const __nv_bfloat16* __restrict__ Bt_lo,
    const float* __restrict__ bias,
    void* __restrict__ Cout)
{
    const uint32_t sb = smem_u32(smem);
    const int tid   = threadIdx.x;
    const int lane  = tid & 31;
    const int wid   = tid >> 5;
    const int mwarp = wid & 1;
    const int nwarp = wid >> 1;
    const size_t rowBase = (size_t)bx * 128;

    float acc[4][8][4];
#pragma unroll
    for (int i = 0; i < 4; i++)
#pragma unroll
        for (int j = 0; j < 8; j++)
#pragma unroll
            for (int r = 0; r < 4; r++) acc[i][j][r] = 0.f;

    const int a_row = lane & 15, a_kh = lane >> 4;
    const uint32_t aAddrHi = sb + V_AHI +
        (uint32_t)(((mwarp * 64 + a_row) * SA + a_kh * 8) * 2);
    const int b_g = lane >> 3, b_r = lane & 7;
    const uint32_t bAddrBase = sb + V_B0 +
        (uint32_t)(((nwarp * 64 + (b_g >> 1) * 8 + b_r) * SA + (b_g & 1) * 8) * 2);

    float4 apre[8];
#pragma unroll
    for (int it = 0; it < 8; it++) {
        int idx = tid + it * 256;
        int row = idx >> 4, q = idx & 15;
        apre[it] = *(const float4*)(A + (rowBase + row) * 256 + 0 + q * 4);
    }
#pragma unroll
    for (int it = 0; it < 8; it++) {
        int idx = tid + it * 256;
        int n = idx >> 3, q = idx & 7;
        uint32_t eoff = (uint32_t)((n * SA + q * 8) * 2);
        CP_ASYNC16(sb + V_B0 + eoff, Bt_hi + (size_t)n * 256 + q * 8);
        CP_ASYNC16(sb + V_B0 + 36864 + eoff, Bt_lo + (size_t)n * 256 + q * 8);
    }
    CP_COMMIT();

#pragma unroll 1
    for (int ch = 0; ch < 4; ch++) {
        const int buf = ch & 1;
#pragma unroll
        for (int it = 0; it < 8; it++) {
            int idx = tid + it * 256;
            int row = idx >> 4, q = idx & 15;
            cvt_split_store(smem, V_AHI, V_ALO,
                            (uint32_t)((row * SA + q * 4) * 2), apre[it]);
        }
        if (ch < 3) {
            const int k1 = (ch + 1) * 64;
            const uint32_t bsm = sb + V_B0 + (uint32_t)((buf ^ 1) * V_BSTRIDE);
#pragma unroll
            for (int it = 0; it < 8; it++) {
                int idx = tid + it * 256;
                int n = idx >> 3, q = idx & 7;
                uint32_t eoff = (uint32_t)((n * SA + q * 8) * 2);
                CP_ASYNC16(bsm + eoff,         Bt_hi + (size_t)n * 256 + k1 + q * 8);
                CP_ASYNC16(bsm + 36864 + eoff, Bt_lo + (size_t)n * 256 + k1 + q * 8);
            }
            CP_COMMIT();
            CP_WAIT(1);
        } else {
            CP_WAIT(0);
        }
        __syncthreads();

        if (ch < 3) {
            const int k1 = (ch + 1) * 64;
#pragma unroll
            for (int it = 0; it < 8; it++) {
                int idx = tid + it * 256;
                int row = idx >> 4, q = idx & 15;
                apre[it] = *(const float4*)(A + (rowBase + row) * 256 + k1 + q * 4);
            }
        }

        const uint32_t bAddrHi = bAddrBase + (uint32_t)(buf * V_BSTRIDE);
#pragma unroll
        for (int ks = 0; ks < 4; ks++) {
            const uint32_t kb = (uint32_t)(ks * 32);
            uint32_t ah[4][4], al[4][4];
#pragma unroll
            for (int mt = 0; mt < 4; mt++) {
                uint32_t ad = aAddrHi + (uint32_t)(mt * 16 * SA * 2) + kb;
                ldsm_x4(ah[mt], ad);
                ldsm_x4(al[mt], ad + (V_ALO - V_AHI));
            }
#pragma unroll
            for (int pr = 0; pr < 4; pr++) {
                uint32_t bh[4], bl[4];
                uint32_t bd = bAddrHi + (uint32_t)(pr * 16 * SA * 2) + kb;
                ldsm_x4(bh, bd);
                ldsm_x4(bl, bd + 36864);
#pragma unroll
                for (int h2 = 0; h2 < 2; h2++) {
                    const int nt = pr * 2 + h2, h = h2 * 2;
#pragma unroll
                    for (int mt = 0; mt < 4; mt++) {
                        mma_bf16(acc[mt][nt], ah[mt], bh[h], bh[h + 1]);
                        mma_bf16(acc[mt][nt], ah[mt], bl[h], bl[h + 1]);
                        mma_bf16(acc[mt][nt], al[mt], bh[h], bh[h + 1]);
                    }
                }
            }
        }
        __syncthreads();
    }

#pragma unroll
    for (int nt = 0; nt < 8; nt++) {
        const int col = nwarp * 64 + nt * 8 + (lane & 3) * 2;
        const float2 bb = *(const float2*)(bias + col);
#pragma unroll
        for (int mt = 0; mt < 4; mt++) {
            const size_t row0 = rowBase + mwarp * 64 + mt * 16 + (lane >> 2);
            if (HALF_OUT) {
                __half* Ch = (__half*)Cout;
                __half2 h0 = __floats2half2_rn(acc[mt][nt][0] + bb.x,
                                               acc[mt][nt][1] + bb.y);
                __half2 h1 = __floats2half2_rn(acc[mt][nt][2] + bb.x,
                                               acc[mt][nt][3] + bb.y);
                *(__half2*)(Ch + row0 * 256 + col)       = h0;
                *(__half2*)(Ch + (row0 + 8) * 256 + col) = h1;
            } else {
                float* Cf = (float*)Cout;
                float2 o0, o1;
                o0.x = acc[mt][nt][0] + bb.x; o0.y = acc[mt][nt][1] + bb.y;
                o1.x = acc[mt][nt][2] + bb.x; o1.y = acc[mt][nt][3] + bb.y;
                *(float2*)(Cf + row0 * 256 + col)       = o0;
                *(float2*)(Cf + (row0 + 8) * 256 + col) = o1;
            }
        }
    }
}

// ---- fat kernel: value GEMM (blocks 0..NVBLK-1) + off/attn GEMM (rest) ----
__global__ __launch_bounds__(256, 1) void fused_gemms_kernel(
    const float* __restrict__ inp,
    const float* __restrict__ query,
    const float* __restrict__ bv)
{
    extern __shared__ char smem[];
    if (blockIdx.x < NVBLK) {
        gemm256_body<true>(smem, blockIdx.x, inp, g_wv_hi, g_wv_lo,
                           bv, g_value);
    } else {
        int b = blockIdx.x - NVBLK;
        gemm128_body(smem, b & 3, b >> 2, query, g_wfa_hi, g_wfa_lo,
                     g_bfa, g_offattn, 512);
    }
}

// out-projection kernel (float out)
__global__ __launch_bounds__(256, 1) void out_gemm_kernel(
    const float* __restrict__ bias, float* __restrict__ out)
{
    extern __shared__ char smem[];
    gemm256_body<false>(smem, blockIdx.x, g_mid, g_wo_hi, g_wo_lo, bias, out);
}

// ---- unified prep ----------------------------------------------------------
__global__ void prep_all_kernel(const float* __restrict__ Wv,
                                const float* __restrict__ Wout,
                                const float* __restrict__ Woff,
                                const float* __restrict__ Wattn,
                                const float* __restrict__ boff,
                                const float* __restrict__ battn)
{
    int idx = blockIdx.x * 256 + threadIdx.x;
    int row = idx >> 8, k = idx & 255;
    float v;
    __nv_bfloat16 *dh, *dl;
    int n;
    if (row < 256)      { n = row;       v = Wv  [k * 256 + n]; dh = g_wv_hi;  dl = g_wv_lo;  }
    else if (row < 512) { n = row - 256; v = Wout[k * 256 + n]; dh = g_wo_hi;  dl = g_wo_lo;  }
    else if (row < 896) { n = row - 512; v = Woff[k * 384 + n]; dh = g_wfa_hi; dl = g_wfa_lo; }
    else                { n = row - 896 + 384;
                          v = Wattn[k * 128 + (row - 896)];     dh = g_wfa_hi; dl = g_wfa_lo; }
    __nv_bfloat16 h = __float2bfloat16(v);
    dh[n * 256 + k] = h;
    dl[n * 256 + k] = __float2bfloat16(v - __bfloat162float(h));

    if (blockIdx.x < 2) {
        int t = blockIdx.x * 256 + threadIdx.x;
        g_bfa[t] = (t < 384) ? boff[t] : battn[t - 384];
    }
}

// ====== fused softmax + trilinear deformable sampling (fp16 value) =========
// (idx, aw) packed int2, even corners in slots 0..63, odd in 64..127, so
// phase 2 reads contiguous int4 (one LDS serves two corners).
__global__ __launch_bounds__(256) void sample_kernel(
    const float* __restrict__ rp,
    const int*   __restrict__ shapes,
    const int*   __restrict__ starts)
{
    const int q    = blockIdx.x;
    const int h    = threadIdx.x >> 5;
    const int lane = threadIdx.x & 31;

    __shared__ float s_rp[NLEV * 3];
    __shared__ int   s_dim[NLEV * 3];
    __shared__ int   s_start[NLEV];
    __shared__ int2  s_pair[NHEADS][128];
    if (threadIdx.x < NLEV * 3) {
        s_rp[threadIdx.x]  = rp[(size_t)q * (NLEV * 3) + threadIdx.x];
        s_dim[threadIdx.x] = shapes[threadIdx.x];
    }
    if (threadIdx.x < NLEV) s_start[threadIdx.x] = starts[threadIdx.x];
    __syncthreads();

    const int n = q / LQ;
    const int o     = lane & 15;        // point 0..15
    const int chalf = lane >> 4;        // corner half
    const int l     = o >> 2;

    float logit = g_offattn[(size_t)q * 512 + 384 + h * 16 + o];
    float m = logit;
#pragma unroll
    for (int s = 8; s > 0; s >>= 1)
        m = fmaxf(m, __shfl_xor_sync(0xffffffffu, m, s, 16));
    float e = __expf(logit - m);
    float ssum = e;
#pragma unroll
    for (int s = 8; s > 0; s >>= 1)
        ssum += __shfl_xor_sync(0xffffffffu, ssum, s, 16);
    const float a = e / ssum;

    const float* offq = g_offattn + (size_t)q * 512 + h * 48 + o * 3;
    const int D = s_dim[l * 3 + 0];
    const int H = s_dim[l * 3 + 1];
    const int W = s_dim[l * 3 + 2];
    const float x = (s_rp[l * 3 + 0] + offq[0] / (float)W) * (float)W - 0.5f;
    const float y = (s_rp[l * 3 + 1] + offq[1] / (float)H) * (float)H - 0.5f;
    const float z = (s_rp[l * 3 + 2] + offq[2] / (float)D) * (float)D - 0.5f;
    const float x0f = floorf(x), y0f = floorf(y), z0f = floorf(z);
    const int   x0 = (int)x0f,   y0 = (int)y0f,   z0 = (int)z0f;
    const float fx = x - x0f,    fy = y - y0f,    fz = z - z0f;

#pragma unroll
    for (int cc = 0; cc < 4; cc++) {
        const int c  = chalf * 4 + cc;
        const int dx = c & 1, dy = (c >> 1) & 1, dz = (c >> 2) & 1;
        const int xi = x0 + dx, yi = y0 + dy, zi = z0 + dz;
        const float w = (dx ? fx : 1.f - fx)
                      * (dy ? fy : 1.f - fy)
                      * (dz ? fz : 1.f - fz);
        const bool valid = (xi >= 0) & (xi < W) & (yi >= 0) & (yi < H) &
                           (zi >= 0) & (zi < D) & (w != 0.f);
        const int cg = o * 8 + c;
        s_pair[h][(cg >> 1) + (cg & 1) * 64] =
            make_int2(valid ? ((zi * H + yi) * W + xi) : -1,
                      __float_as_int(a * w));
    }
    __syncwarp();

    // ---- phase 2: int4 LDS (2 corners) + half2 gathers ----
    const int half = lane >> 4;          // corner parity handled by this lane
    const int ch2  = lane & 15;          // channel pair
    const __half* vb[NLEV];
#pragma unroll
    for (int lv = 0; lv < NLEV; lv++)
        vb[lv] = g_value + ((size_t)(n * LEN_IN + s_start[lv])) * DM
               + h * DHEAD + ch2 * 2;

    const int2* pbase = &s_pair[h][half * 64];
    float ax = 0.f, ay = 0.f;
#pragma unroll
    for (int i = 0; i < 64; i += 2) {
        int4 pk = *(const int4*)(pbase + i);   // corners i and i+1 of this parity
        const int lv = i >> 4;                 // level constant across the pair
        if (pk.x >= 0) {
            float2 vf = __half22float2(
                __ldg((const __half2*)(vb[lv] + (size_t)pk.x * DM)));
            const float aw = __int_as_float(pk.y);
            ax = fmaf(aw, vf.x, ax);
            ay = fmaf(aw, vf.y, ay);
        }
        if (pk.z >= 0) {
            float2 vf = __half22float2(
                __ldg((const __half2*)(vb[lv] + (size_t)pk.z * DM)));
            const float aw = __int_as_float(pk.w);
            ax = fmaf(aw, vf.x, ax);
            ay = fmaf(aw, vf.y, ay);
        }
    }
    ax += __shfl_xor_sync(0xffffffffu, ax, 16);
    ay += __shfl_xor_sync(0xffffffffu, ay, 16);
    if (lane < 16)
        *(float2*)(g_mid + (size_t)q * DM + h * DHEAD + ch2 * 2) =
            make_float2(ax, ay);
}

// ---------------------------------------------------------------------------
extern "C" void kernel_launch(void* const* d_in, const int* in_sizes, int n_in,
                              void* d_out, int out_size)
{
    const float* query  = (const float*)d_in[0];
    const float* refp   = (const float*)d_in[1];
    const float* inp    = (const float*)d_in[2];
    const int*   shapes = (const int*)  d_in[3];
    const int*   starts = (const int*)  d_in[4];
    const float* Wv     = (const float*)d_in[5];
    const float* bv     = (const float*)d_in[6];
    const float* Woff   = (const float*)d_in[7];
    const float* boff   = (const float*)d_in[8];
    const float* Wattn  = (const float*)d_in[9];
    const float* battn  = (const float*)d_in[10];
    const float* Wout   = (const float*)d_in[11];
    const float* bout   = (const float*)d_in[12];
    float* out = (float*)d_out;

    cudaFuncSetAttribute(fused_gemms_kernel,
                         cudaFuncAttributeMaxDynamicSharedMemorySize, SMEM_V);
    cudaFuncSetAttribute(out_gemm_kernel,
                         cudaFuncAttributeMaxDynamicSharedMemorySize, SMEM_V);

    // 0) prep all transposed bf16 splits + fused off/attn bias
    prep_all_kernel<<<1024, 256>>>(Wv, Wout, Woff, Wattn, boff, battn);

    // 1) fused: value GEMM (fp16 out) + [off|attn] GEMM
    fused_gemms_kernel<<<NVBLK + 512, 256, SMEM_V>>>(inp, query, bv);

    // 2) fused softmax + deformable trilinear sampling -> g_mid
    sample_kernel<<<NB * LQ, 256>>>(refp, shapes, starts);

    // 3) out = g_mid @ Wout + bout
    out_gemm_kernel<<<(NB * LQ) / 128, 256, SMEM_V>>>(bout, out);
}

// round 12
// speedup vs baseline: 1.2161x; 1.0473x over previous
#include <cuda_runtime.h>
#include <cuda_bf16.h>
#include <cuda_fp16.h>
#include <math.h>
#include <stdint.h>

#define NB      2
#define LQ      8192
#define LEN_IN  149760
#define DM      256
#define NHEADS  8
#define NLEV    4
#define NPTS    4
#define DHEAD   32
#define NVBLK   (((NB * LEN_IN) / 128) * 2)   // 4680 value blocks (N-split 2)

// ---------------- scratch (device globals; no cudaMalloc allowed) ----------
__device__ __half g_value[(size_t)NB * LEN_IN * DM];                     // 153 MB
__device__ float  g_offattn[(size_t)NB * LQ * 512];                     // off 0..383, logits 384..511
__device__ float  g_mid  [(size_t)NB * LQ * DM];                        // 16 MB
__device__ __nv_bfloat16 g_wv_hi [DM * DM];
__device__ __nv_bfloat16 g_wv_lo [DM * DM];
__device__ __nv_bfloat16 g_wo_hi [DM * DM];
__device__ __nv_bfloat16 g_wo_lo [DM * DM];
__device__ __nv_bfloat16 g_wfa_hi[512 * DM];
__device__ __nv_bfloat16 g_wfa_lo[512 * DM];
__device__ float  g_bfa[512];

// ============================ PTX helpers ===================================
__device__ __forceinline__ uint32_t smem_u32(const void* p) {
    uint32_t a;
    asm("{ .reg .u64 t; cvta.to.shared.u64 t, %1; cvt.u32.u64 %0, t; }" : "=r"(a) : "l"(p));
    return a;
}
__device__ __forceinline__ void ldsm_x4(uint32_t* r, uint32_t addr) {
    asm volatile("ldmatrix.sync.aligned.m8n8.x4.shared.b16 {%0,%1,%2,%3}, [%4];"
        : "=r"(r[0]), "=r"(r[1]), "=r"(r[2]), "=r"(r[3]) : "r"(addr));
}
__device__ __forceinline__ void mma_bf16(float* d, const uint32_t* a,
                                         uint32_t b0, uint32_t b1) {
    asm volatile(
        "mma.sync.aligned.m16n8k16.row.col.f32.bf16.bf16.f32 "
        "{%0,%1,%2,%3}, {%4,%5,%6,%7}, {%8,%9}, {%0,%1,%2,%3};"
        : "+f"(d[0]), "+f"(d[1]), "+f"(d[2]), "+f"(d[3])
        : "r"(a[0]), "r"(a[1]), "r"(a[2]), "r"(a[3]), "r"(b0), "r"(b1));
}
#define CP_ASYNC16(dst, src) \
    asm volatile("cp.async.cg.shared.global [%0], [%1], 16;" :: "r"(dst), "l"(src))
#define CP_COMMIT() asm volatile("cp.async.commit_group;" ::: "memory")
#define CP_WAIT(n)  asm volatile("cp.async.wait_group %0;" :: "n"(n) : "memory")

__device__ __forceinline__ void cvt_split_store(char* smem, int offHi, int offLo,
                                                uint32_t eoff, float4 v) {
    __nv_bfloat162 h01 = __floats2bfloat162_rn(v.x, v.y);
    __nv_bfloat162 h23 = __floats2bfloat162_rn(v.z, v.w);
    float lx = v.x - __bfloat162float(__low2bfloat16(h01));
    float ly = v.y - __bfloat162float(__high2bfloat16(h01));
    float lz = v.z - __bfloat162float(__low2bfloat16(h23));
    float lw = v.w - __bfloat162float(__high2bfloat16(h23));
    __nv_bfloat162 l01 = __floats2bfloat162_rn(lx, ly);
    __nv_bfloat162 l23 = __floats2bfloat162_rn(lz, lw);
    *(uint2*)(smem + offHi + eoff) = make_uint2(*(uint32_t*)&h01, *(uint32_t*)&h23);
    *(uint2*)(smem + offLo + eoff) = make_uint2(*(uint32_t*)&l01, *(uint32_t*)&l23);
}

#define SA        72

// ======== pipelined 128x128-tile GEMM body, 2 CTAs/SM ========
// SMEM: A_hi 0 (18KB), A_lo 18432 (18KB),
//       B buf{0,1} at 36864 + buf*36864 (hi at +0, lo at +18432)
// total 110592 B -> two CTAs fit in 216KB of the 228KB carveout.
#define P_AHI     0
#define P_ALO     18432
#define P_B0      36864
#define P_BSTRIDE 36864
#define SMEM_P    110592

template <bool HALF_OUT>
__device__ __forceinline__ void gemm128_pipe(
    char* smem, int bn, int bm,
    const float* __restrict__ A,
    const __nv_bfloat16* __restrict__ Bt_hi,
    const __nv_bfloat16* __restrict__ Bt_lo,
    const float* __restrict__ bias,
    void* __restrict__ Cout, int Nc)
{
    const uint32_t sb = smem_u32(smem);
    const int tid   = threadIdx.x;
    const int lane  = tid & 31;
    const int wid   = tid >> 5;
    const int mwarp = wid & 1;          // 64 rows
    const int nwarp = wid >> 1;         // 32 cols
    const size_t rowBase = (size_t)bm * 128;

    float acc[4][4][4];
#pragma unroll
    for (int i = 0; i < 4; i++)
#pragma unroll
        for (int j = 0; j < 4; j++)
#pragma unroll
            for (int r = 0; r < 4; r++) acc[i][j][r] = 0.f;

    const int a_row = lane & 15, a_kh = lane >> 4;
    const uint32_t aAddrHi = sb + P_AHI +
        (uint32_t)(((mwarp * 64 + a_row) * SA + a_kh * 8) * 2);
    const int b_g = lane >> 3, b_r = lane & 7;
    const uint32_t bAddrBase = sb + P_B0 +
        (uint32_t)(((nwarp * 32 + (b_g >> 1) * 8 + b_r) * SA + (b_g & 1) * 8) * 2);

    // prologue: cp.async B(0) into buf 0
#pragma unroll
    for (int it = 0; it < 4; it++) {
        int idx = tid + it * 256;            // 0..1023 uint4 slots
        int n = idx >> 3, q = idx & 7;
        uint32_t eoff = (uint32_t)((n * SA + q * 8) * 2);
        size_t goff = (size_t)(bn * 128 + n) * 256 + q * 8;
        CP_ASYNC16(sb + P_B0 + eoff,         Bt_hi + goff);
        CP_ASYNC16(sb + P_B0 + 18432 + eoff, Bt_lo + goff);
    }
    CP_COMMIT();

#pragma unroll 1
    for (int ch = 0; ch < 4; ch++) {
        const int buf = ch & 1;
        const int k0 = ch * 64;

        // A chunk: 128x64 f32 -> split bf16 smem
#pragma unroll
        for (int it = 0; it < 8; it++) {
            int idx = tid + it * 256;
            int row = idx >> 4, q = idx & 15;
            float4 v = *(const float4*)(A + (rowBase + row) * 256 + k0 + q * 4);
            cvt_split_store(smem, P_AHI, P_ALO,
                            (uint32_t)((row * SA + q * 4) * 2), v);
        }
        // B(ch+1) cp.async into other buffer
        if (ch < 3) {
            const int k1 = k0 + 64;
            const uint32_t bsm = sb + P_B0 + (uint32_t)((buf ^ 1) * P_BSTRIDE);
#pragma unroll
            for (int it = 0; it < 4; it++) {
                int idx = tid + it * 256;
                int n = idx >> 3, q = idx & 7;
                uint32_t eoff = (uint32_t)((n * SA + q * 8) * 2);
                size_t goff = (size_t)(bn * 128 + n) * 256 + k1 + q * 8;
                CP_ASYNC16(bsm + eoff,         Bt_hi + goff);
                CP_ASYNC16(bsm + 18432 + eoff, Bt_lo + goff);
            }
            CP_COMMIT();
            CP_WAIT(1);        // B(ch) resident, B(ch+1) in flight
        } else {
            CP_WAIT(0);
        }
        __syncthreads();

        const uint32_t bAddrHi = bAddrBase + (uint32_t)(buf * P_BSTRIDE);
#pragma unroll
        for (int ks = 0; ks < 4; ks++) {
            const uint32_t kb = (uint32_t)(ks * 32);
            uint32_t ah[4][4], al[4][4];
#pragma unroll
            for (int mt = 0; mt < 4; mt++) {
                uint32_t ad = aAddrHi + (uint32_t)(mt * 16 * SA * 2) + kb;
                ldsm_x4(ah[mt], ad);
                ldsm_x4(al[mt], ad + (P_ALO - P_AHI));
            }
            uint32_t bh[2][4], bl[2][4];
#pragma unroll
            for (int pr = 0; pr < 2; pr++) {
                uint32_t bd = bAddrHi + (uint32_t)(pr * 16 * SA * 2) + kb;
                ldsm_x4(bh[pr], bd);
                ldsm_x4(bl[pr], bd + 18432);
            }
#pragma unroll
            for (int mt = 0; mt < 4; mt++)
#pragma unroll
                for (int nt = 0; nt < 4; nt++) {
                    const int pr = nt >> 1, h = (nt & 1) * 2;
                    mma_bf16(acc[mt][nt], ah[mt], bh[pr][h], bh[pr][h + 1]);
                    mma_bf16(acc[mt][nt], ah[mt], bl[pr][h], bl[pr][h + 1]);
                    mma_bf16(acc[mt][nt], al[mt], bh[pr][h], bh[pr][h + 1]);
                }
        }
        __syncthreads();
    }

    // epilogue
#pragma unroll
    for (int nt = 0; nt < 4; nt++) {
        const int col = bn * 128 + nwarp * 32 + nt * 8 + (lane & 3) * 2;
        const float2 bb = *(const float2*)(bias + col);
#pragma unroll
        for (int mt = 0; mt < 4; mt++) {
            const size_t row0 = rowBase + mwarp * 64 + mt * 16 + (lane >> 2);
            if (HALF_OUT) {
                __half* Ch = (__half*)Cout;
                __half2 h0 = __floats2half2_rn(acc[mt][nt][0] + bb.x,
                                               acc[mt][nt][1] + bb.y);
                __half2 h1 = __floats2half2_rn(acc[mt][nt][2] + bb.x,
                                               acc[mt][nt][3] + bb.y);
                *(__half2*)(Ch + row0 * Nc + col)       = h0;
                *(__half2*)(Ch + (row0 + 8) * Nc + col) = h1;
            } else {
                float* Cf = (float*)Cout;
                float2 o0, o1;
                o0.x = acc[mt][nt][0] + bb.x; o0.y = acc[mt][nt][1] + bb.y;
                o1.x = acc[mt][nt][2] + bb.x; o1.y = acc[mt][nt][3] + bb.y;
                *(float2*)(Cf + row0 * Nc + col)       = o0;
                *(float2*)(Cf + (row0 + 8) * Nc + col) = o1;
            }
        }
    }
}

// ---- fat kernel: value GEMM (blocks 0..NVBLK-1) + off/attn GEMM (rest) ----
__global__ __launch_bounds__(256, 2) void fused_gemms_kernel(
    const float* __restrict__ inp,
    const float* __restrict__ query,
    const float* __restrict__ bv)
{
    extern __shared__ char smem[];
    const int b = blockIdx.x;
    if (b < NVBLK) {
        gemm128_pipe<true>(smem, b & 1, b >> 1, inp, g_wv_hi, g_wv_lo,
                           bv, g_value, 256);
    } else {
        const int c = b - NVBLK;
        gemm128_pipe<false>(smem, c & 3, c >> 2, query, g_wfa_hi, g_wfa_lo,
                            g_bfa, g_offattn, 512);
    }
}

// out-projection kernel (float out), 2-way N split
__global__ __launch_bounds__(256, 2) void out_gemm_kernel(
    const float* __restrict__ bias, float* __restrict__ out)
{
    extern __shared__ char smem[];
    const int b = blockIdx.x;
    gemm128_pipe<false>(smem, b & 1, b >> 1, g_mid, g_wo_hi, g_wo_lo,
                        bias, out, 256);
}

// ---- unified prep ----------------------------------------------------------
__global__ void prep_all_kernel(const float* __restrict__ Wv,
                                const float* __restrict__ Wout,
                                const float* __restrict__ Woff,
                                const float* __restrict__ Wattn,
                                const float* __restrict__ boff,
                                const float* __restrict__ battn)
{
    int idx = blockIdx.x * 256 + threadIdx.x;
    int row = idx >> 8, k = idx & 255;
    float v;
    __nv_bfloat16 *dh, *dl;
    int n;
    if (row < 256)      { n = row;       v = Wv  [k * 256 + n]; dh = g_wv_hi;  dl = g_wv_lo;  }
    else if (row < 512) { n = row - 256; v = Wout[k * 256 + n]; dh = g_wo_hi;  dl = g_wo_lo;  }
    else if (row < 896) { n = row - 512; v = Woff[k * 384 + n]; dh = g_wfa_hi; dl = g_wfa_lo; }
    else                { n = row - 896 + 384;
                          v = Wattn[k * 128 + (row - 896)];     dh = g_wfa_hi; dl = g_wfa_lo; }
    __nv_bfloat16 h = __float2bfloat16(v);
    dh[n * 256 + k] = h;
    dl[n * 256 + k] = __float2bfloat16(v - __bfloat162float(h));

    if (blockIdx.x < 2) {
        int t = blockIdx.x * 256 + threadIdx.x;
        g_bfa[t] = (t < 384) ? boff[t] : battn[t - 384];
    }
}

// ====== fused softmax + trilinear deformable sampling (fp16 value) =========
__global__ __launch_bounds__(256) void sample_kernel(
    const float* __restrict__ rp,
    const int*   __restrict__ shapes,
    const int*   __restrict__ starts)
{
    const int q    = blockIdx.x;
    const int h    = threadIdx.x >> 5;
    const int lane = threadIdx.x & 31;

    __shared__ float s_rp[NLEV * 3];
    __shared__ int   s_dim[NLEV * 3];
    __shared__ int   s_start[NLEV];
    __shared__ int2  s_pair[NHEADS][128];
    if (threadIdx.x < NLEV * 3) {
        s_rp[threadIdx.x]  = rp[(size_t)q * (NLEV * 3) + threadIdx.x];
        s_dim[threadIdx.x] = shapes[threadIdx.x];
    }
    if (threadIdx.x < NLEV) s_start[threadIdx.x] = starts[threadIdx.x];
    __syncthreads();

    const int n = q / LQ;
    const int o     = lane & 15;
    const int chalf = lane >> 4;
    const int l     = o >> 2;

    float logit = g_offattn[(size_t)q * 512 + 384 + h * 16 + o];
    float m = logit;
#pragma unroll
    for (int s = 8; s > 0; s >>= 1)
        m = fmaxf(m, __shfl_xor_sync(0xffffffffu, m, s, 16));
    float e = __expf(logit - m);
    float ssum = e;
#pragma unroll
    for (int s = 8; s > 0; s >>= 1)
        ssum += __shfl_xor_sync(0xffffffffu, ssum, s, 16);
    const float a = e / ssum;

    const float* offq = g_offattn + (size_t)q * 512 + h * 48 + o * 3;
    const int D = s_dim[l * 3 + 0];
    const int H = s_dim[l * 3 + 1];
    const int W = s_dim[l * 3 + 2];
    const float x = (s_rp[l * 3 + 0] + offq[0] / (float)W) * (float)W - 0.5f;
    const float y = (s_rp[l * 3 + 1] + offq[1] / (float)H) * (float)H - 0.5f;
    const float z = (s_rp[l * 3 + 2] + offq[2] / (float)D) * (float)D - 0.5f;
    const float x0f = floorf(x), y0f = floorf(y), z0f = floorf(z);
    const int   x0 = (int)x0f,   y0 = (int)y0f,   z0 = (int)z0f;
    const float fx = x - x0f,    fy = y - y0f,    fz = z - z0f;

#pragma unroll
    for (int cc = 0; cc < 4; cc++) {
        const int c  = chalf * 4 + cc;
        const int dx = c & 1, dy = (c >> 1) & 1, dz = (c >> 2) & 1;
        const int xi = x0 + dx, yi = y0 + dy, zi = z0 + dz;
        const float w = (dx ? fx : 1.f - fx)
                      * (dy ? fy : 1.f - fy)
                      * (dz ? fz : 1.f - fz);
        const bool valid = (xi >= 0) & (xi < W) & (yi >= 0) & (yi < H) &
                           (zi >= 0) & (zi < D) & (w != 0.f);
        const int cg = o * 8 + c;
        s_pair[h][(cg >> 1) + (cg & 1) * 64] =
            make_int2(valid ? ((zi * H + yi) * W + xi) : -1,
                      __float_as_int(a * w));
    }
    __syncwarp();

    const int half = lane >> 4;
    const int ch2  = lane & 15;
    const __half* vb[NLEV];
#pragma unroll
    for (int lv = 0; lv < NLEV; lv++)
        vb[lv] = g_value + ((size_t)(n * LEN_IN + s_start[lv])) * DM
               + h * DHEAD + ch2 * 2;

    const int2* pbase = &s_pair[h][half * 64];
    float ax = 0.f, ay = 0.f;
#pragma unroll
    for (int i = 0; i < 64; i += 2) {
        int4 pk = *(const int4*)(pbase + i);
        const int lv = i >> 4;
        if (pk.x >= 0) {
            float2 vf = __half22float2(
                __ldg((const __half2*)(vb[lv] + (size_t)pk.x * DM)));
            const float aw = __int_as_float(pk.y);
            ax = fmaf(aw, vf.x, ax);
            ay = fmaf(aw, vf.y, ay);
        }
        if (pk.z >= 0) {
            float2 vf = __half22float2(
                __ldg((const __half2*)(vb[lv] + (size_t)pk.z * DM)));
            const float aw = __int_as_float(pk.w);
            ax = fmaf(aw, vf.x, ax);
            ay = fmaf(aw, vf.y, ay);
        }
    }
    ax += __shfl_xor_sync(0xffffffffu, ax, 16);
    ay += __shfl_xor_sync(0xffffffffu, ay, 16);
    if (lane < 16)
        *(float2*)(g_mid + (size_t)q * DM + h * DHEAD + ch2 * 2) =
            make_float2(ax, ay);
}

// ---------------------------------------------------------------------------
extern "C" void kernel_launch(void* const* d_in, const int* in_sizes, int n_in,
                              void* d_out, int out_size)
{
    const float* query  = (const float*)d_in[0];
    const float* refp   = (const float*)d_in[1];
    const float* inp    = (const float*)d_in[2];
    const int*   shapes = (const int*)  d_in[3];
    const int*   starts = (const int*)  d_in[4];
    const float* Wv     = (const float*)d_in[5];
    const float* bv     = (const float*)d_in[6];
    const float* Woff   = (const float*)d_in[7];
    const float* boff   = (const float*)d_in[8];
    const float* Wattn  = (const float*)d_in[9];
    const float* battn  = (const float*)d_in[10];
    const float* Wout   = (const float*)d_in[11];
    const float* bout   = (const float*)d_in[12];
    float* out = (float*)d_out;

    cudaFuncSetAttribute(fused_gemms_kernel,
                         cudaFuncAttributeMaxDynamicSharedMemorySize, SMEM_P);
    cudaFuncSetAttribute(out_gemm_kernel,
                         cudaFuncAttributeMaxDynamicSharedMemorySize, SMEM_P);

    // 0) prep all transposed bf16 splits + fused off/attn bias
    prep_all_kernel<<<1024, 256>>>(Wv, Wout, Woff, Wattn, boff, battn);

    // 1) fused: value GEMM (fp16 out, N-split 2) + [off|attn] GEMM
    fused_gemms_kernel<<<NVBLK + 512, 256, SMEM_P>>>(inp, query, bv);

    // 2) fused softmax + deformable trilinear sampling -> g_mid
    sample_kernel<<<NB * LQ, 256>>>(refp, shapes, starts);

    // 3) out = g_mid @ Wout + bout  (N-split 2)
    out_gemm_kernel<<<(NB * LQ) / 128 * 2, 256, SMEM_P>>>(bout, out);
}

// round 13
// speedup vs baseline: 1.2341x; 1.0148x over previous
#include <cuda_runtime.h>
#include <cuda_bf16.h>
#include <cuda_fp16.h>
#include <math.h>
#include <stdint.h>

#define NB      2
#define LQ      8192
#define LEN_IN  149760
#define DM      256
#define NHEADS  8
#define NLEV    4
#define NPTS    4
#define DHEAD   32
#define NVBLK   (((NB * LEN_IN) / 128) * 2)   // 4680 value blocks (N-split 2)

// ---------------- scratch (device globals; no cudaMalloc allowed) ----------
__device__ __half g_value[(size_t)NB * LEN_IN * DM];                     // 153 MB
__device__ float  g_offattn[(size_t)NB * LQ * 512];                     // off 0..383, logits 384..511
__device__ float  g_mid  [(size_t)NB * LQ * DM];                        // 16 MB
__device__ __nv_bfloat16 g_wv_hi [DM * DM];
__device__ __nv_bfloat16 g_wv_lo [DM * DM];
__device__ __nv_bfloat16 g_wo_hi [DM * DM];
__device__ __nv_bfloat16 g_wo_lo [DM * DM];
__device__ __nv_bfloat16 g_wfa_hi[512 * DM];
__device__ __nv_bfloat16 g_wfa_lo[512 * DM];
__device__ float  g_bfa[512];

// ============================ PTX helpers ===================================
__device__ __forceinline__ uint32_t smem_u32(const void* p) {
    uint32_t a;
    asm("{ .reg .u64 t; cvta.to.shared.u64 t, %1; cvt.u32.u64 %0, t; }" : "=r"(a) : "l"(p));
    return a;
}
__device__ __forceinline__ void ldsm_x4(uint32_t* r, uint32_t addr) {
    asm volatile("ldmatrix.sync.aligned.m8n8.x4.shared.b16 {%0,%1,%2,%3}, [%4];"
        : "=r"(r[0]), "=r"(r[1]), "=r"(r[2]), "=r"(r[3]) : "r"(addr));
}
__device__ __forceinline__ void mma_bf16(float* d, const uint32_t* a,
                                         uint32_t b0, uint32_t b1) {
    asm volatile(
        "mma.sync.aligned.m16n8k16.row.col.f32.bf16.bf16.f32 "
        "{%0,%1,%2,%3}, {%4,%5,%6,%7}, {%8,%9}, {%0,%1,%2,%3};"
        : "+f"(d[0]), "+f"(d[1]), "+f"(d[2]), "+f"(d[3])
        : "r"(a[0]), "r"(a[1]), "r"(a[2]), "r"(a[3]), "r"(b0), "r"(b1));
}
#define CP_ASYNC16(dst, src) \
    asm volatile("cp.async.cg.shared.global [%0], [%1], 16;" :: "r"(dst), "l"(src))
#define CP_COMMIT() asm volatile("cp.async.commit_group;" ::: "memory")
#define CP_WAIT(n)  asm volatile("cp.async.wait_group %0;" :: "n"(n) : "memory")

__device__ __forceinline__ void cvt_split_store(char* smem, int offHi, int offLo,
                                                uint32_t eoff, float4 v) {
    __nv_bfloat162 h01 = __floats2bfloat162_rn(v.x, v.y);
    __nv_bfloat162 h23 = __floats2bfloat162_rn(v.z, v.w);
    float lx = v.x - __bfloat162float(__low2bfloat16(h01));
    float ly = v.y - __bfloat162float(__high2bfloat16(h01));
    float lz = v.z - __bfloat162float(__low2bfloat16(h23));
    float lw = v.w - __bfloat162float(__high2bfloat16(h23));
    __nv_bfloat162 l01 = __floats2bfloat162_rn(lx, ly);
    __nv_bfloat162 l23 = __floats2bfloat162_rn(lz, lw);
    *(uint2*)(smem + offHi + eoff) = make_uint2(*(uint32_t*)&h01, *(uint32_t*)&h23);
    *(uint2*)(smem + offLo + eoff) = make_uint2(*(uint32_t*)&l01, *(uint32_t*)&l23);
}

#define SA        72

// ======== pipelined 128x128-tile GEMM body, 2 CTAs/SM ========
#define P_AHI     0
#define P_ALO     18432
#define P_B0      36864
#define P_BSTRIDE 36864
#define SMEM_P    110592

template <bool HALF_OUT>
__device__ __forceinline__ void gemm128_pipe(
    char* smem, int bn, int bm,
    const float* __restrict__ A,
    const __nv_bfloat16* __restrict__ Bt_hi,
    const __nv_bfloat16* __restrict__ Bt_lo,
    const float* __restrict__ bias,
    void* __restrict__ Cout, int Nc)
{
    const uint32_t sb = smem_u32(smem);
    const int tid   = threadIdx.x;
    const int lane  = tid & 31;
    const int wid   = tid >> 5;
    const int mwarp = wid & 1;
    const int nwarp = wid >> 1;
    const size_t rowBase = (size_t)bm * 128;

    float acc[4][4][4];
#pragma unroll
    for (int i = 0; i < 4; i++)
#pragma unroll
        for (int j = 0; j < 4; j++)
#pragma unroll
            for (int r = 0; r < 4; r++) acc[i][j][r] = 0.f;

    const int a_row = lane & 15, a_kh = lane >> 4;
    const uint32_t aAddrHi = sb + P_AHI +
        (uint32_t)(((mwarp * 64 + a_row) * SA + a_kh * 8) * 2);
    const int b_g = lane >> 3, b_r = lane & 7;
    const uint32_t bAddrBase = sb + P_B0 +
        (uint32_t)(((nwarp * 32 + (b_g >> 1) * 8 + b_r) * SA + (b_g & 1) * 8) * 2);

    // prologue: cp.async B(0) into buf 0
#pragma unroll
    for (int it = 0; it < 4; it++) {
        int idx = tid + it * 256;
        int n = idx >> 3, q = idx & 7;
        uint32_t eoff = (uint32_t)((n * SA + q * 8) * 2);
        size_t goff = (size_t)(bn * 128 + n) * 256 + q * 8;
        CP_ASYNC16(sb + P_B0 + eoff,         Bt_hi + goff);
        CP_ASYNC16(sb + P_B0 + 18432 + eoff, Bt_lo + goff);
    }
    CP_COMMIT();

#pragma unroll 1
    for (int ch = 0; ch < 4; ch++) {
        const int buf = ch & 1;
        const int k0 = ch * 64;

#pragma unroll
        for (int it = 0; it < 8; it++) {
            int idx = tid + it * 256;
            int row = idx >> 4, q = idx & 15;
            float4 v = *(const float4*)(A + (rowBase + row) * 256 + k0 + q * 4);
            cvt_split_store(smem, P_AHI, P_ALO,
                            (uint32_t)((row * SA + q * 4) * 2), v);
        }
        if (ch < 3) {
            const int k1 = k0 + 64;
            const uint32_t bsm = sb + P_B0 + (uint32_t)((buf ^ 1) * P_BSTRIDE);
#pragma unroll
            for (int it = 0; it < 4; it++) {
                int idx = tid + it * 256;
                int n = idx >> 3, q = idx & 7;
                uint32_t eoff = (uint32_t)((n * SA + q * 8) * 2);
                size_t goff = (size_t)(bn * 128 + n) * 256 + k1 + q * 8;
                CP_ASYNC16(bsm + eoff,         Bt_hi + goff);
                CP_ASYNC16(bsm + 18432 + eoff, Bt_lo + goff);
            }
            CP_COMMIT();
            CP_WAIT(1);
        } else {
            CP_WAIT(0);
        }
        __syncthreads();

        const uint32_t bAddrHi = bAddrBase + (uint32_t)(buf * P_BSTRIDE);
#pragma unroll
        for (int ks = 0; ks < 4; ks++) {
            const uint32_t kb = (uint32_t)(ks * 32);
            uint32_t ah[4][4], al[4][4];
#pragma unroll
            for (int mt = 0; mt < 4; mt++) {
                uint32_t ad = aAddrHi + (uint32_t)(mt * 16 * SA * 2) + kb;
                ldsm_x4(ah[mt], ad);
                ldsm_x4(al[mt], ad + (P_ALO - P_AHI));
            }
            uint32_t bh[2][4], bl[2][4];
#pragma unroll
            for (int pr = 0; pr < 2; pr++) {
                uint32_t bd = bAddrHi + (uint32_t)(pr * 16 * SA * 2) + kb;
                ldsm_x4(bh[pr], bd);
                ldsm_x4(bl[pr], bd + 18432);
            }
#pragma unroll
            for (int mt = 0; mt < 4; mt++)
#pragma unroll
                for (int nt = 0; nt < 4; nt++) {
                    const int pr = nt >> 1, h = (nt & 1) * 2;
                    mma_bf16(acc[mt][nt], ah[mt], bh[pr][h], bh[pr][h + 1]);
                    mma_bf16(acc[mt][nt], ah[mt], bl[pr][h], bl[pr][h + 1]);
                    mma_bf16(acc[mt][nt], al[mt], bh[pr][h], bh[pr][h + 1]);
                }
        }
        __syncthreads();
    }

#pragma unroll
    for (int nt = 0; nt < 4; nt++) {
        const int col = bn * 128 + nwarp * 32 + nt * 8 + (lane & 3) * 2;
        const float2 bb = *(const float2*)(bias + col);
#pragma unroll
        for (int mt = 0; mt < 4; mt++) {
            const size_t row0 = rowBase + mwarp * 64 + mt * 16 + (lane >> 2);
            if (HALF_OUT) {
                __half* Ch = (__half*)Cout;
                __half2 h0 = __floats2half2_rn(acc[mt][nt][0] + bb.x,
                                               acc[mt][nt][1] + bb.y);
                __half2 h1 = __floats2half2_rn(acc[mt][nt][2] + bb.x,
                                               acc[mt][nt][3] + bb.y);
                *(__half2*)(Ch + row0 * Nc + col)       = h0;
                *(__half2*)(Ch + (row0 + 8) * Nc + col) = h1;
            } else {
                float* Cf = (float*)Cout;
                float2 o0, o1;
                o0.x = acc[mt][nt][0] + bb.x; o0.y = acc[mt][nt][1] + bb.y;
                o1.x = acc[mt][nt][2] + bb.x; o1.y = acc[mt][nt][3] + bb.y;
                *(float2*)(Cf + row0 * Nc + col)       = o0;
                *(float2*)(Cf + (row0 + 8) * Nc + col) = o1;
            }
        }
    }
}

// ---- fat kernel: value GEMM (blocks 0..NVBLK-1) + off/attn GEMM (rest) ----
__global__ __launch_bounds__(256, 2) void fused_gemms_kernel(
    const float* __restrict__ inp,
    const float* __restrict__ query,
    const float* __restrict__ bv)
{
    extern __shared__ char smem[];
    const int b = blockIdx.x;
    if (b < NVBLK) {
        gemm128_pipe<true>(smem, b & 1, b >> 1, inp, g_wv_hi, g_wv_lo,
                           bv, g_value, 256);
    } else {
        const int c = b - NVBLK;
        gemm128_pipe<false>(smem, c & 3, c >> 2, query, g_wfa_hi, g_wfa_lo,
                            g_bfa, g_offattn, 512);
    }
}

// out-projection kernel (float out), 2-way N split
__global__ __launch_bounds__(256, 2) void out_gemm_kernel(
    const float* __restrict__ bias, float* __restrict__ out)
{
    extern __shared__ char smem[];
    const int b = blockIdx.x;
    gemm128_pipe<false>(smem, b & 1, b >> 1, g_mid, g_wo_hi, g_wo_lo,
                        bias, out, 256);
}

// ---- unified prep ----------------------------------------------------------
__global__ void prep_all_kernel(const float* __restrict__ Wv,
                                const float* __restrict__ Wout,
                                const float* __restrict__ Woff,
                                const float* __restrict__ Wattn,
                                const float* __restrict__ boff,
                                const float* __restrict__ battn)
{
    int idx = blockIdx.x * 256 + threadIdx.x;
    int row = idx >> 8, k = idx & 255;
    float v;
    __nv_bfloat16 *dh, *dl;
    int n;
    if (row < 256)      { n = row;       v = Wv  [k * 256 + n]; dh = g_wv_hi;  dl = g_wv_lo;  }
    else if (row < 512) { n = row - 256; v = Wout[k * 256 + n]; dh = g_wo_hi;  dl = g_wo_lo;  }
    else if (row < 896) { n = row - 512; v = Woff[k * 384 + n]; dh = g_wfa_hi; dl = g_wfa_lo; }
    else                { n = row - 896 + 384;
                          v = Wattn[k * 128 + (row - 896)];     dh = g_wfa_hi; dl = g_wfa_lo; }
    __nv_bfloat16 h = __float2bfloat16(v);
    dh[n * 256 + k] = h;
    dl[n * 256 + k] = __float2bfloat16(v - __bfloat162float(h));

    if (blockIdx.x < 2) {
        int t = blockIdx.x * 256 + threadIdx.x;
        g_bfa[t] = (t < 384) ? boff[t] : battn[t - 384];
    }
}

// ====== fused softmax + trilinear deformable sampling (fp16 value) =========
// Phase 2 processes 4 corners per iteration: lane = (g = lane>>3, ch4 = lane&7);
// each lane gathers uint2 (4 fp16 channels) for corner 4i+g. Level pointer
// hoisted (level constant across 8 consecutive iterations).
__global__ __launch_bounds__(256) void sample_kernel(
    const float* __restrict__ rp,
    const int*   __restrict__ shapes,
    const int*   __restrict__ starts)
{
    const int q    = blockIdx.x;
    const int h    = threadIdx.x >> 5;
    const int lane = threadIdx.x & 31;

    __shared__ float s_rp[NLEV * 3];
    __shared__ int   s_dim[NLEV * 3];
    __shared__ int   s_start[NLEV];
    __shared__ int2  s_pair[NHEADS][128];
    if (threadIdx.x < NLEV * 3) {
        s_rp[threadIdx.x]  = rp[(size_t)q * (NLEV * 3) + threadIdx.x];
        s_dim[threadIdx.x] = shapes[threadIdx.x];
    }
    if (threadIdx.x < NLEV) s_start[threadIdx.x] = starts[threadIdx.x];
    __syncthreads();

    const int n = q / LQ;
    const int o     = lane & 15;        // point 0..15
    const int chalf = lane >> 4;        // corner half
    const int l     = o >> 2;

    // softmax over 16 logits
    float logit = g_offattn[(size_t)q * 512 + 384 + h * 16 + o];
    float m = logit;
#pragma unroll
    for (int s = 8; s > 0; s >>= 1)
        m = fmaxf(m, __shfl_xor_sync(0xffffffffu, m, s, 16));
    float e = __expf(logit - m);
    float ssum = e;
#pragma unroll
    for (int s = 8; s > 0; s >>= 1)
        ssum += __shfl_xor_sync(0xffffffffu, ssum, s, 16);
    const float a = e / ssum;

    const float* offq = g_offattn + (size_t)q * 512 + h * 48 + o * 3;
    const int D = s_dim[l * 3 + 0];
    const int H = s_dim[l * 3 + 1];
    const int W = s_dim[l * 3 + 2];
    const float x = (s_rp[l * 3 + 0] + offq[0] / (float)W) * (float)W - 0.5f;
    const float y = (s_rp[l * 3 + 1] + offq[1] / (float)H) * (float)H - 0.5f;
    const float z = (s_rp[l * 3 + 2] + offq[2] / (float)D) * (float)D - 0.5f;
    const float x0f = floorf(x), y0f = floorf(y), z0f = floorf(z);
    const int   x0 = (int)x0f,   y0 = (int)y0f,   z0 = (int)z0f;
    const float fx = x - x0f,    fy = y - y0f,    fz = z - z0f;

#pragma unroll
    for (int cc = 0; cc < 4; cc++) {
        const int c  = chalf * 4 + cc;
        const int dx = c & 1, dy = (c >> 1) & 1, dz = (c >> 2) & 1;
        const int xi = x0 + dx, yi = y0 + dy, zi = z0 + dz;
        const float w = (dx ? fx : 1.f - fx)
                      * (dy ? fy : 1.f - fy)
                      * (dz ? fz : 1.f - fz);
        const bool valid = (xi >= 0) & (xi < W) & (yi >= 0) & (yi < H) &
                           (zi >= 0) & (zi < D) & (w != 0.f);
        s_pair[h][o * 8 + c] =
            make_int2(valid ? ((zi * H + yi) * W + xi) : -1,
                      __float_as_int(a * w));
    }
    __syncwarp();

    // ---- phase 2: 4 corners per iteration ----
    const int g   = lane >> 3;           // corner subgroup 0..3
    const int ch4 = lane & 7;            // channel quad 0..7

    const int2* ph = s_pair[h];
    float a0 = 0.f, a1 = 0.f, a2 = 0.f, a3 = 0.f;

#pragma unroll
    for (int lv = 0; lv < NLEV; lv++) {
        const __half* vbl = g_value
            + ((size_t)(n * LEN_IN + s_start[lv])) * DM
            + h * DHEAD + ch4 * 4;
#pragma unroll
        for (int i8 = 0; i8 < 8; i8++) {
            const int i = lv * 8 + i8;            // iteration 0..31
            int2 pk = ph[i * 4 + g];              // broadcast LDS.64
            if (pk.x >= 0) {
                uint2 raw = __ldg((const uint2*)(vbl + (size_t)pk.x * DM));
                float2 f0 = __half22float2(*(__half2*)&raw.x);
                float2 f1 = __half22float2(*(__half2*)&raw.y);
                const float aw = __int_as_float(pk.y);
                a0 = fmaf(aw, f0.x, a0);
                a1 = fmaf(aw, f0.y, a1);
                a2 = fmaf(aw, f1.x, a2);
                a3 = fmaf(aw, f1.y, a3);
            }
        }
    }

    // reduce across the 4 corner subgroups (lanes l, l+8, l+16, l+24)
#pragma unroll
    for (int s = 8; s <= 16; s <<= 1) {
        a0 += __shfl_xor_sync(0xffffffffu, a0, s);
        a1 += __shfl_xor_sync(0xffffffffu, a1, s);
        a2 += __shfl_xor_sync(0xffffffffu, a2, s);
        a3 += __shfl_xor_sync(0xffffffffu, a3, s);
    }
    if (lane < 8) {
        float4 o4 = make_float4(a0, a1, a2, a3);
        *(float4*)(g_mid + (size_t)q * DM + h * DHEAD + ch4 * 4) = o4;
    }
}

// ---------------------------------------------------------------------------
extern "C" void kernel_launch(void* const* d_in, const int* in_sizes, int n_in,
                              void* d_out, int out_size)
{
    const float* query  = (const float*)d_in[0];
    const float* refp   = (const float*)d_in[1];
    const float* inp    = (const float*)d_in[2];
    const int*   shapes = (const int*)  d_in[3];
    const int*   starts = (const int*)  d_in[4];
    const float* Wv     = (const float*)d_in[5];
    const float* bv     = (const float*)d_in[6];
    const float* Woff   = (const float*)d_in[7];
    const float* boff   = (const float*)d_in[8];
    const float* Wattn  = (const float*)d_in[9];
    const float* battn  = (const float*)d_in[10];
    const float* Wout   = (const float*)d_in[11];
    const float* bout   = (const float*)d_in[12];
    float* out = (float*)d_out;

    cudaFuncSetAttribute(fused_gemms_kernel,
                         cudaFuncAttributeMaxDynamicSharedMemorySize, SMEM_P);
    cudaFuncSetAttribute(out_gemm_kernel,
                         cudaFuncAttributeMaxDynamicSharedMemorySize, SMEM_P);

    // 0) prep all transposed bf16 splits + fused off/attn bias
    prep_all_kernel<<<1024, 256>>>(Wv, Wout, Woff, Wattn, boff, battn);

    // 1) fused: value GEMM (fp16 out, N-split 2) + [off|attn] GEMM
    fused_gemms_kernel<<<NVBLK + 512, 256, SMEM_P>>>(inp, query, bv);

    // 2) fused softmax + deformable trilinear sampling -> g_mid
    sample_kernel<<<NB * LQ, 256>>>(refp, shapes, starts);

    // 3) out = g_mid @ Wout + bout  (N-split 2)
    out_gemm_kernel<<<(NB * LQ) / 128 * 2, 256, SMEM_P>>>(bout, out);
}

// round 14
// speedup vs baseline: 1.2544x; 1.0165x over previous
#include <cuda_runtime.h>
#include <cuda_bf16.h>
#include <cuda_fp16.h>
#include <math.h>
#include <stdint.h>

#define NB      2
#define LQ      8192
#define LEN_IN  149760
#define DM      256
#define NHEADS  8
#define NLEV    4
#define NPTS    4
#define DHEAD   32
#define NVBLK   (((NB * LEN_IN) / 128) * 2)   // 4680 value blocks (N-split 2)

// ---------------- scratch (device globals; no cudaMalloc allowed) ----------
__device__ __half g_value[(size_t)NB * LEN_IN * DM];                     // 153 MB
__device__ float  g_offattn[(size_t)NB * LQ * 512];                     // off 0..383, logits 384..511
__device__ float  g_mid  [(size_t)NB * LQ * DM];                        // 16 MB
__device__ __nv_bfloat16 g_wv_hi [DM * DM];
__device__ __nv_bfloat16 g_wv_lo [DM * DM];
__device__ __nv_bfloat16 g_wo_hi [DM * DM];
__device__ __nv_bfloat16 g_wo_lo [DM * DM];
__device__ __nv_bfloat16 g_wfa_hi[512 * DM];
__device__ __nv_bfloat16 g_wfa_lo[512 * DM];
__device__ float  g_bfa[512];

// ============================ PTX helpers ===================================
__device__ __forceinline__ uint32_t smem_u32(const void* p) {
    uint32_t a;
    asm("{ .reg .u64 t; cvta.to.shared.u64 t, %1; cvt.u32.u64 %0, t; }" : "=r"(a) : "l"(p));
    return a;
}
__device__ __forceinline__ void ldsm_x4(uint32_t* r, uint32_t addr) {
    asm volatile("ldmatrix.sync.aligned.m8n8.x4.shared.b16 {%0,%1,%2,%3}, [%4];"
        : "=r"(r[0]), "=r"(r[1]), "=r"(r[2]), "=r"(r[3]) : "r"(addr));
}
__device__ __forceinline__ void mma_bf16(float* d, const uint32_t* a,
                                         uint32_t b0, uint32_t b1) {
    asm volatile(
        "mma.sync.aligned.m16n8k16.row.col.f32.bf16.bf16.f32 "
        "{%0,%1,%2,%3}, {%4,%5,%6,%7}, {%8,%9}, {%0,%1,%2,%3};"
        : "+f"(d[0]), "+f"(d[1]), "+f"(d[2]), "+f"(d[3])
        : "r"(a[0]), "r"(a[1]), "r"(a[2]), "r"(a[3]), "r"(b0), "r"(b1));
}
#define CP_ASYNC16(dst, src) \
    asm volatile("cp.async.cg.shared.global [%0], [%1], 16;" :: "r"(dst), "l"(src))
#define CP_COMMIT() asm volatile("cp.async.commit_group;" ::: "memory")
#define CP_WAIT(n)  asm volatile("cp.async.wait_group %0;" :: "n"(n) : "memory")

__device__ __forceinline__ void cvt_split_store(char* smem, int offHi, int offLo,
                                                uint32_t eoff, float4 v) {
    __nv_bfloat162 h01 = __floats2bfloat162_rn(v.x, v.y);
    __nv_bfloat162 h23 = __floats2bfloat162_rn(v.z, v.w);
    float lx = v.x - __bfloat162float(__low2bfloat16(h01));
    float ly = v.y - __bfloat162float(__high2bfloat16(h01));
    float lz = v.z - __bfloat162float(__low2bfloat16(h23));
    float lw = v.w - __bfloat162float(__high2bfloat16(h23));
    __nv_bfloat162 l01 = __floats2bfloat162_rn(lx, ly);
    __nv_bfloat162 l23 = __floats2bfloat162_rn(lz, lw);
    *(uint2*)(smem + offHi + eoff) = make_uint2(*(uint32_t*)&h01, *(uint32_t*)&h23);
    *(uint2*)(smem + offLo + eoff) = make_uint2(*(uint32_t*)&l01, *(uint32_t*)&l23);
}

#define SA        72

// ======== pipelined 128x128-tile GEMM body, 2 CTAs/SM ========
#define P_AHI     0
#define P_ALO     18432
#define P_B0      36864
#define P_BSTRIDE 36864
#define SMEM_P    110592

template <bool HALF_OUT>
__device__ __forceinline__ void gemm128_pipe(
    char* smem, int bn, int bm,
    const float* __restrict__ A,
    const __nv_bfloat16* __restrict__ Bt_hi,
    const __nv_bfloat16* __restrict__ Bt_lo,
    const float* __restrict__ bias,
    void* __restrict__ Cout, int Nc)
{
    const uint32_t sb = smem_u32(smem);
    const int tid   = threadIdx.x;
    const int lane  = tid & 31;
    const int wid   = tid >> 5;
    const int mwarp = wid & 1;
    const int nwarp = wid >> 1;
    const size_t rowBase = (size_t)bm * 128;

    float acc[4][4][4];
#pragma unroll
    for (int i = 0; i < 4; i++)
#pragma unroll
        for (int j = 0; j < 4; j++)
#pragma unroll
            for (int r = 0; r < 4; r++) acc[i][j][r] = 0.f;

    const int a_row = lane & 15, a_kh = lane >> 4;
    const uint32_t aAddrHi = sb + P_AHI +
        (uint32_t)(((mwarp * 64 + a_row) * SA + a_kh * 8) * 2);
    const int b_g = lane >> 3, b_r = lane & 7;
    const uint32_t bAddrBase = sb + P_B0 +
        (uint32_t)(((nwarp * 32 + (b_g >> 1) * 8 + b_r) * SA + (b_g & 1) * 8) * 2);

    // prologue: cp.async B(0) into buf 0
#pragma unroll
    for (int it = 0; it < 4; it++) {
        int idx = tid + it * 256;
        int n = idx >> 3, q = idx & 7;
        uint32_t eoff = (uint32_t)((n * SA + q * 8) * 2);
        size_t goff = (size_t)(bn * 128 + n) * 256 + q * 8;
        CP_ASYNC16(sb + P_B0 + eoff,         Bt_hi + goff);
        CP_ASYNC16(sb + P_B0 + 18432 + eoff, Bt_lo + goff);
    }
    CP_COMMIT();

#pragma unroll 1
    for (int ch = 0; ch < 4; ch++) {
        const int buf = ch & 1;
        const int k0 = ch * 64;

#pragma unroll
        for (int it = 0; it < 8; it++) {
            int idx = tid + it * 256;
            int row = idx >> 4, q = idx & 15;
            float4 v = *(const float4*)(A + (rowBase + row) * 256 + k0 + q * 4);
            cvt_split_store(smem, P_AHI, P_ALO,
                            (uint32_t)((row * SA + q * 4) * 2), v);
        }
        if (ch < 3) {
            const int k1 = k0 + 64;
            const uint32_t bsm = sb + P_B0 + (uint32_t)((buf ^ 1) * P_BSTRIDE);
#pragma unroll
            for (int it = 0; it < 4; it++) {
                int idx = tid + it * 256;
                int n = idx >> 3, q = idx & 7;
                uint32_t eoff = (uint32_t)((n * SA + q * 8) * 2);
                size_t goff = (size_t)(bn * 128 + n) * 256 + k1 + q * 8;
                CP_ASYNC16(bsm + eoff,         Bt_hi + goff);
                CP_ASYNC16(bsm + 18432 + eoff, Bt_lo + goff);
            }
            CP_COMMIT();
            CP_WAIT(1);
        } else {
            CP_WAIT(0);
        }
        __syncthreads();

        const uint32_t bAddrHi = bAddrBase + (uint32_t)(buf * P_BSTRIDE);
#pragma unroll
        for (int ks = 0; ks < 4; ks++) {
            const uint32_t kb = (uint32_t)(ks * 32);
            uint32_t ah[4][4], al[4][4];
#pragma unroll
            for (int mt = 0; mt < 4; mt++) {
                uint32_t ad = aAddrHi + (uint32_t)(mt * 16 * SA * 2) + kb;
                ldsm_x4(ah[mt], ad);
                ldsm_x4(al[mt], ad + (P_ALO - P_AHI));
            }
            uint32_t bh[2][4], bl[2][4];
#pragma unroll
            for (int pr = 0; pr < 2; pr++) {
                uint32_t bd = bAddrHi + (uint32_t)(pr * 16 * SA * 2) + kb;
                ldsm_x4(bh[pr], bd);
                ldsm_x4(bl[pr], bd + 18432);
            }
#pragma unroll
            for (int mt = 0; mt < 4; mt++)
#pragma unroll
                for (int nt = 0; nt < 4; nt++) {
                    const int pr = nt >> 1, h = (nt & 1) * 2;
                    mma_bf16(acc[mt][nt], ah[mt], bh[pr][h], bh[pr][h + 1]);
                    mma_bf16(acc[mt][nt], ah[mt], bl[pr][h], bl[pr][h + 1]);
                    mma_bf16(acc[mt][nt], al[mt], bh[pr][h], bh[pr][h + 1]);
                }
        }
        __syncthreads();
    }

#pragma unroll
    for (int nt = 0; nt < 4; nt++) {
        const int col = bn * 128 + nwarp * 32 + nt * 8 + (lane & 3) * 2;
        const float2 bb = *(const float2*)(bias + col);
#pragma unroll
        for (int mt = 0; mt < 4; mt++) {
            const size_t row0 = rowBase + mwarp * 64 + mt * 16 + (lane >> 2);
            if (HALF_OUT) {
                __half* Ch = (__half*)Cout;
                __half2 h0 = __floats2half2_rn(acc[mt][nt][0] + bb.x,
                                               acc[mt][nt][1] + bb.y);
                __half2 h1 = __floats2half2_rn(acc[mt][nt][2] + bb.x,
                                               acc[mt][nt][3] + bb.y);
                *(__half2*)(Ch + row0 * Nc + col)       = h0;
                *(__half2*)(Ch + (row0 + 8) * Nc + col) = h1;
            } else {
                float* Cf = (float*)Cout;
                float2 o0, o1;
                o0.x = acc[mt][nt][0] + bb.x; o0.y = acc[mt][nt][1] + bb.y;
                o1.x = acc[mt][nt][2] + bb.x; o1.y = acc[mt][nt][3] + bb.y;
                *(float2*)(Cf + row0 * Nc + col)       = o0;
                *(float2*)(Cf + (row0 + 8) * Nc + col) = o1;
            }
        }
    }
}

// ---- fat kernel: value GEMM (blocks 0..NVBLK-1) + off/attn GEMM (rest) ----
__global__ __launch_bounds__(256, 2) void fused_gemms_kernel(
    const float* __restrict__ inp,
    const float* __restrict__ query,
    const float* __restrict__ bv)
{
    extern __shared__ char smem[];
    const int b = blockIdx.x;
    if (b < NVBLK) {
        gemm128_pipe<true>(smem, b & 1, b >> 1, inp, g_wv_hi, g_wv_lo,
                           bv, g_value, 256);
    } else {
        const int c = b - NVBLK;
        gemm128_pipe<false>(smem, c & 3, c >> 2, query, g_wfa_hi, g_wfa_lo,
                            g_bfa, g_offattn, 512);
    }
}

// out-projection kernel (float out), 2-way N split
__global__ __launch_bounds__(256, 2) void out_gemm_kernel(
    const float* __restrict__ bias, float* __restrict__ out)
{
    extern __shared__ char smem[];
    const int b = blockIdx.x;
    gemm128_pipe<false>(smem, b & 1, b >> 1, g_mid, g_wo_hi, g_wo_lo,
                        bias, out, 256);
}

// ---- unified prep ----------------------------------------------------------
__global__ void prep_all_kernel(const float* __restrict__ Wv,
                                const float* __restrict__ Wout,
                                const float* __restrict__ Woff,
                                const float* __restrict__ Wattn,
                                const float* __restrict__ boff,
                                const float* __restrict__ battn)
{
    int idx = blockIdx.x * 256 + threadIdx.x;
    int row = idx >> 8, k = idx & 255;
    float v;
    __nv_bfloat16 *dh, *dl;
    int n;
    if (row < 256)      { n = row;       v = Wv  [k * 256 + n]; dh = g_wv_hi;  dl = g_wv_lo;  }
    else if (row < 512) { n = row - 256; v = Wout[k * 256 + n]; dh = g_wo_hi;  dl = g_wo_lo;  }
    else if (row < 896) { n = row - 512; v = Woff[k * 384 + n]; dh = g_wfa_hi; dl = g_wfa_lo; }
    else                { n = row - 896 + 384;
                          v = Wattn[k * 128 + (row - 896)];     dh = g_wfa_hi; dl = g_wfa_lo; }
    __nv_bfloat16 h = __float2bfloat16(v);
    dh[n * 256 + k] = h;
    dl[n * 256 + k] = __float2bfloat16(v - __bfloat162float(h));

    if (blockIdx.x < 2) {
        int t = blockIdx.x * 256 + threadIdx.x;
        g_bfa[t] = (t < 384) ? boff[t] : battn[t - 384];
    }
}

// ====== fused softmax + trilinear deformable sampling (fp16 value) =========
// Branchless gathers: invalid corners clamp idx to 0 and zero the weight,
// so every iteration issues an unconditional LDG (better batching / no
// predication), multiply-by-zero keeps correctness.
__global__ __launch_bounds__(256) void sample_kernel(
    const float* __restrict__ rp,
    const int*   __restrict__ shapes,
    const int*   __restrict__ starts)
{
    const int q    = blockIdx.x;
    const int h    = threadIdx.x >> 5;
    const int lane = threadIdx.x & 31;

    __shared__ float s_rp[NLEV * 3];
    __shared__ int   s_dim[NLEV * 3];
    __shared__ int   s_start[NLEV];
    __shared__ int2  s_pair[NHEADS][128];
    if (threadIdx.x < NLEV * 3) {
        s_rp[threadIdx.x]  = rp[(size_t)q * (NLEV * 3) + threadIdx.x];
        s_dim[threadIdx.x] = shapes[threadIdx.x];
    }
    if (threadIdx.x < NLEV) s_start[threadIdx.x] = starts[threadIdx.x];
    __syncthreads();

    const int n = q / LQ;
    const int o     = lane & 15;        // point 0..15
    const int chalf = lane >> 4;        // corner half
    const int l     = o >> 2;

    // softmax over 16 logits
    float logit = g_offattn[(size_t)q * 512 + 384 + h * 16 + o];
    float m = logit;
#pragma unroll
    for (int s = 8; s > 0; s >>= 1)
        m = fmaxf(m, __shfl_xor_sync(0xffffffffu, m, s, 16));
    float e = __expf(logit - m);
    float ssum = e;
#pragma unroll
    for (int s = 8; s > 0; s >>= 1)
        ssum += __shfl_xor_sync(0xffffffffu, ssum, s, 16);
    const float a = e / ssum;

    const float* offq = g_offattn + (size_t)q * 512 + h * 48 + o * 3;
    const int D = s_dim[l * 3 + 0];
    const int H = s_dim[l * 3 + 1];
    const int W = s_dim[l * 3 + 2];
    const float x = (s_rp[l * 3 + 0] + offq[0] / (float)W) * (float)W - 0.5f;
    const float y = (s_rp[l * 3 + 1] + offq[1] / (float)H) * (float)H - 0.5f;
    const float z = (s_rp[l * 3 + 2] + offq[2] / (float)D) * (float)D - 0.5f;
    const float x0f = floorf(x), y0f = floorf(y), z0f = floorf(z);
    const int   x0 = (int)x0f,   y0 = (int)y0f,   z0 = (int)z0f;
    const float fx = x - x0f,    fy = y - y0f,    fz = z - z0f;

#pragma unroll
    for (int cc = 0; cc < 4; cc++) {
        const int c  = chalf * 4 + cc;
        const int dx = c & 1, dy = (c >> 1) & 1, dz = (c >> 2) & 1;
        const int xi = x0 + dx, yi = y0 + dy, zi = z0 + dz;
        const float w = (dx ? fx : 1.f - fx)
                      * (dy ? fy : 1.f - fy)
                      * (dz ? fz : 1.f - fz);
        const bool valid = (xi >= 0) & (xi < W) & (yi >= 0) & (yi < H) &
                           (zi >= 0) & (zi < D);
        // branchless: clamp index into range, zero the weight when invalid
        const int idxc = valid ? ((zi * H + yi) * W + xi) : 0;
        s_pair[h][o * 8 + c] =
            make_int2(idxc, __float_as_int(valid ? a * w : 0.f));
    }
    __syncwarp();

    // ---- phase 2: 4 corners per iteration, unconditional gathers ----
    const int g   = lane >> 3;           // corner subgroup 0..3
    const int ch4 = lane & 7;            // channel quad 0..7

    const int2* ph = s_pair[h];
    float a0 = 0.f, a1 = 0.f, a2 = 0.f, a3 = 0.f;

#pragma unroll
    for (int lv = 0; lv < NLEV; lv++) {
        const __half* vbl = g_value
            + ((size_t)(n * LEN_IN + s_start[lv])) * DM
            + h * DHEAD + ch4 * 4;
#pragma unroll
        for (int i8 = 0; i8 < 8; i8++) {
            const int i = lv * 8 + i8;            // iteration 0..31
            int2 pk = ph[i * 4 + g];              // broadcast LDS.64
            uint2 raw = __ldg((const uint2*)(vbl + (size_t)pk.x * DM));
            const float aw = __int_as_float(pk.y);
            float2 f0 = __half22float2(*(__half2*)&raw.x);
            float2 f1 = __half22float2(*(__half2*)&raw.y);
            a0 = fmaf(aw, f0.x, a0);
            a1 = fmaf(aw, f0.y, a1);
            a2 = fmaf(aw, f1.x, a2);
            a3 = fmaf(aw, f1.y, a3);
        }
    }

    // reduce across the 4 corner subgroups
#pragma unroll
    for (int s = 8; s <= 16; s <<= 1) {
        a0 += __shfl_xor_sync(0xffffffffu, a0, s);
        a1 += __shfl_xor_sync(0xffffffffu, a1, s);
        a2 += __shfl_xor_sync(0xffffffffu, a2, s);
        a3 += __shfl_xor_sync(0xffffffffu, a3, s);
    }
    if (lane < 8) {
        float4 o4 = make_float4(a0, a1, a2, a3);
        *(float4*)(g_mid + (size_t)q * DM + h * DHEAD + ch4 * 4) = o4;
    }
}

// ---------------------------------------------------------------------------
extern "C" void kernel_launch(void* const* d_in, const int* in_sizes, int n_in,
                              void* d_out, int out_size)
{
    const float* query  = (const float*)d_in[0];
    const float* refp   = (const float*)d_in[1];
    const float* inp    = (const float*)d_in[2];
    const int*   shapes = (const int*)  d_in[3];
    const int*   starts = (const int*)  d_in[4];
    const float* Wv     = (const float*)d_in[5];
    const float* bv     = (const float*)d_in[6];
    const float* Woff   = (const float*)d_in[7];
    const float* boff   = (const float*)d_in[8];
    const float* Wattn  = (const float*)d_in[9];
    const float* battn  = (const float*)d_in[10];
    const float* Wout   = (const float*)d_in[11];
    const float* bout   = (const float*)d_in[12];
    float* out = (float*)d_out;

    cudaFuncSetAttribute(fused_gemms_kernel,
                         cudaFuncAttributeMaxDynamicSharedMemorySize, SMEM_P);
    cudaFuncSetAttribute(out_gemm_kernel,
                         cudaFuncAttributeMaxDynamicSharedMemorySize, SMEM_P);

    // 0) prep all transposed bf16 splits + fused off/attn bias
    prep_all_kernel<<<1024, 256>>>(Wv, Wout, Woff, Wattn, boff, battn);

    // 1) fused: value GEMM (fp16 out, N-split 2) + [off|attn] GEMM
    fused_gemms_kernel<<<NVBLK + 512, 256, SMEM_P>>>(inp, query, bv);

    // 2) fused softmax + deformable trilinear sampling -> g_mid
    sample_kernel<<<NB * LQ, 256>>>(refp, shapes, starts);

    // 3) out = g_mid @ Wout + bout  (N-split 2)
    out_gemm_kernel<<<(NB * LQ) / 128 * 2, 256, SMEM_P>>>(bout, out);
}

// round 15
// speedup vs baseline: 1.4850x; 1.1838x over previous
#include <cuda_runtime.h>
#include <cuda_bf16.h>
#include <cuda_fp16.h>
#include <math.h>
#include <stdint.h>

#define NB      2
#define LQ      8192
#define LEN_IN  149760
#define DM      256
#define NHEADS  8
#define NLEV    4
#define NPTS    4
#define DHEAD   32
#define NVBLK   (((NB * LEN_IN) / 128) * 2)   // 4680 value blocks (N-split 2)

// ---------------- scratch (device globals; no cudaMalloc allowed) ----------
__device__ __half g_value[(size_t)NB * LEN_IN * DM];                     // 153 MB
__device__ float  g_offattn[(size_t)NB * LQ * 512];                     // off 0..383, logits 384..511
__device__ float  g_mid  [(size_t)NB * LQ * DM];                        // 16 MB
__device__ __half        g_wv_h  [DM * DM];        // Wv^T fp16 hi
__device__ __half        g_wv_l  [DM * DM];        // Wv^T fp16 lo
__device__ __nv_bfloat16 g_wo_hi [DM * DM];
__device__ __nv_bfloat16 g_wo_lo [DM * DM];
__device__ __nv_bfloat16 g_wfa_hi[512 * DM];
__device__ __nv_bfloat16 g_wfa_lo[512 * DM];
__device__ float  g_bfa[512];

// ============================ PTX helpers ===================================
__device__ __forceinline__ uint32_t smem_u32(const void* p) {
    uint32_t a;
    asm("{ .reg .u64 t; cvta.to.shared.u64 t, %1; cvt.u32.u64 %0, t; }" : "=r"(a) : "l"(p));
    return a;
}
__device__ __forceinline__ void ldsm_x4(uint32_t* r, uint32_t addr) {
    asm volatile("ldmatrix.sync.aligned.m8n8.x4.shared.b16 {%0,%1,%2,%3}, [%4];"
        : "=r"(r[0]), "=r"(r[1]), "=r"(r[2]), "=r"(r[3]) : "r"(addr));
}
__device__ __forceinline__ void mma_bf16(float* d, const uint32_t* a,
                                         uint32_t b0, uint32_t b1) {
    asm volatile(
        "mma.sync.aligned.m16n8k16.row.col.f32.bf16.bf16.f32 "
        "{%0,%1,%2,%3}, {%4,%5,%6,%7}, {%8,%9}, {%0,%1,%2,%3};"
        : "+f"(d[0]), "+f"(d[1]), "+f"(d[2]), "+f"(d[3])
        : "r"(a[0]), "r"(a[1]), "r"(a[2]), "r"(a[3]), "r"(b0), "r"(b1));
}
__device__ __forceinline__ void mma_f16(float* d, const uint32_t* a,
                                        uint32_t b0, uint32_t b1) {
    asm volatile(
        "mma.sync.aligned.m16n8k16.row.col.f32.f16.f16.f32 "
        "{%0,%1,%2,%3}, {%4,%5,%6,%7}, {%8,%9}, {%0,%1,%2,%3};"
        : "+f"(d[0]), "+f"(d[1]), "+f"(d[2]), "+f"(d[3])
        : "r"(a[0]), "r"(a[1]), "r"(a[2]), "r"(a[3]), "r"(b0), "r"(b1));
}
#define CP_ASYNC16(dst, src) \
    asm volatile("cp.async.cg.shared.global [%0], [%1], 16;" :: "r"(dst), "l"(src))
#define CP_COMMIT() asm volatile("cp.async.commit_group;" ::: "memory")
#define CP_WAIT(n)  asm volatile("cp.async.wait_group %0;" :: "n"(n) : "memory")

__device__ __forceinline__ void cvt_split_store(char* smem, int offHi, int offLo,
                                                uint32_t eoff, float4 v) {
    __nv_bfloat162 h01 = __floats2bfloat162_rn(v.x, v.y);
    __nv_bfloat162 h23 = __floats2bfloat162_rn(v.z, v.w);
    float lx = v.x - __bfloat162float(__low2bfloat16(h01));
    float ly = v.y - __bfloat162float(__high2bfloat16(h01));
    float lz = v.z - __bfloat162float(__low2bfloat16(h23));
    float lw = v.w - __bfloat162float(__high2bfloat16(h23));
    __nv_bfloat162 l01 = __floats2bfloat162_rn(lx, ly);
    __nv_bfloat162 l23 = __floats2bfloat162_rn(lz, lw);
    *(uint2*)(smem + offHi + eoff) = make_uint2(*(uint32_t*)&h01, *(uint32_t*)&h23);
    *(uint2*)(smem + offLo + eoff) = make_uint2(*(uint32_t*)&l01, *(uint32_t*)&l23);
}

#define SA        72

// ======== pipelined 128x128-tile GEMM, 3-product bf16 (off/attn/out) ========
#define P_AHI     0
#define P_ALO     18432
#define P_B0      36864
#define P_BSTRIDE 36864
#define SMEM_P    110592

template <bool HALF_OUT>
__device__ __forceinline__ void gemm128_pipe(
    char* smem, int bn, int bm,
    const float* __restrict__ A,
    const __nv_bfloat16* __restrict__ Bt_hi,
    const __nv_bfloat16* __restrict__ Bt_lo,
    const float* __restrict__ bias,
    void* __restrict__ Cout, int Nc)
{
    const uint32_t sb = smem_u32(smem);
    const int tid   = threadIdx.x;
    const int lane  = tid & 31;
    const int wid   = tid >> 5;
    const int mwarp = wid & 1;
    const int nwarp = wid >> 1;
    const size_t rowBase = (size_t)bm * 128;

    float acc[4][4][4];
#pragma unroll
    for (int i = 0; i < 4; i++)
#pragma unroll
        for (int j = 0; j < 4; j++)
#pragma unroll
            for (int r = 0; r < 4; r++) acc[i][j][r] = 0.f;

    const int a_row = lane & 15, a_kh = lane >> 4;
    const uint32_t aAddrHi = sb + P_AHI +
        (uint32_t)(((mwarp * 64 + a_row) * SA + a_kh * 8) * 2);
    const int b_g = lane >> 3, b_r = lane & 7;
    const uint32_t bAddrBase = sb + P_B0 +
        (uint32_t)(((nwarp * 32 + (b_g >> 1) * 8 + b_r) * SA + (b_g & 1) * 8) * 2);

#pragma unroll
    for (int it = 0; it < 4; it++) {
        int idx = tid + it * 256;
        int n = idx >> 3, q = idx & 7;
        uint32_t eoff = (uint32_t)((n * SA + q * 8) * 2);
        size_t goff = (size_t)(bn * 128 + n) * 256 + q * 8;
        CP_ASYNC16(sb + P_B0 + eoff,         Bt_hi + goff);
        CP_ASYNC16(sb + P_B0 + 18432 + eoff, Bt_lo + goff);
    }
    CP_COMMIT();

#pragma unroll 1
    for (int ch = 0; ch < 4; ch++) {
        const int buf = ch & 1;
        const int k0 = ch * 64;

#pragma unroll
        for (int it = 0; it < 8; it++) {
            int idx = tid + it * 256;
            int row = idx >> 4, q = idx & 15;
            float4 v = *(const float4*)(A + (rowBase + row) * 256 + k0 + q * 4);
            cvt_split_store(smem, P_AHI, P_ALO,
                            (uint32_t)((row * SA + q * 4) * 2), v);
        }
        if (ch < 3) {
            const int k1 = k0 + 64;
            const uint32_t bsm = sb + P_B0 + (uint32_t)((buf ^ 1) * P_BSTRIDE);
#pragma unroll
            for (int it = 0; it < 4; it++) {
                int idx = tid + it * 256;
                int n = idx >> 3, q = idx & 7;
                uint32_t eoff = (uint32_t)((n * SA + q * 8) * 2);
                size_t goff = (size_t)(bn * 128 + n) * 256 + k1 + q * 8;
                CP_ASYNC16(bsm + eoff,         Bt_hi + goff);
                CP_ASYNC16(bsm + 18432 + eoff, Bt_lo + goff);
            }
            CP_COMMIT();
            CP_WAIT(1);
        } else {
            CP_WAIT(0);
        }
        __syncthreads();

        const uint32_t bAddrHi = bAddrBase + (uint32_t)(buf * P_BSTRIDE);
#pragma unroll
        for (int ks = 0; ks < 4; ks++) {
            const uint32_t kb = (uint32_t)(ks * 32);
            uint32_t ah[4][4], al[4][4];
#pragma unroll
            for (int mt = 0; mt < 4; mt++) {
                uint32_t ad = aAddrHi + (uint32_t)(mt * 16 * SA * 2) + kb;
                ldsm_x4(ah[mt], ad);
                ldsm_x4(al[mt], ad + (P_ALO - P_AHI));
            }
            uint32_t bh[2][4], bl[2][4];
#pragma unroll
            for (int pr = 0; pr < 2; pr++) {
                uint32_t bd = bAddrHi + (uint32_t)(pr * 16 * SA * 2) + kb;
                ldsm_x4(bh[pr], bd);
                ldsm_x4(bl[pr], bd + 18432);
            }
#pragma unroll
            for (int mt = 0; mt < 4; mt++)
#pragma unroll
                for (int nt = 0; nt < 4; nt++) {
                    const int pr = nt >> 1, h = (nt & 1) * 2;
                    mma_bf16(acc[mt][nt], ah[mt], bh[pr][h], bh[pr][h + 1]);
                    mma_bf16(acc[mt][nt], ah[mt], bl[pr][h], bl[pr][h + 1]);
                    mma_bf16(acc[mt][nt], al[mt], bh[pr][h], bh[pr][h + 1]);
                }
        }
        __syncthreads();
    }

#pragma unroll
    for (int nt = 0; nt < 4; nt++) {
        const int col = bn * 128 + nwarp * 32 + nt * 8 + (lane & 3) * 2;
        const float2 bb = *(const float2*)(bias + col);
#pragma unroll
        for (int mt = 0; mt < 4; mt++) {
            const size_t row0 = rowBase + mwarp * 64 + mt * 16 + (lane >> 2);
            if (HALF_OUT) {
                __half* Ch = (__half*)Cout;
                __half2 h0 = __floats2half2_rn(acc[mt][nt][0] + bb.x,
                                               acc[mt][nt][1] + bb.y);
                __half2 h1 = __floats2half2_rn(acc[mt][nt][2] + bb.x,
                                               acc[mt][nt][3] + bb.y);
                *(__half2*)(Ch + row0 * Nc + col)       = h0;
                *(__half2*)(Ch + (row0 + 8) * Nc + col) = h1;
            } else {
                float* Cf = (float*)Cout;
                float2 o0, o1;
                o0.x = acc[mt][nt][0] + bb.x; o0.y = acc[mt][nt][1] + bb.y;
                o1.x = acc[mt][nt][2] + bb.x; o1.y = acc[mt][nt][3] + bb.y;
                *(float2*)(Cf + row0 * Nc + col)       = o0;
                *(float2*)(Cf + (row0 + 8) * Nc + col) = o1;
            }
        }
    }
}

// ======== pipelined 128x128-tile GEMM, 2-product fp16 (value path) =========
// A single fp16 (18KB at 0); B fp16 hi+lo double-buffered at 18432 (+36864/buf).
#define F_A       0
#define F_B0      18432
#define F_BSTRIDE 36864

__device__ __forceinline__ void gemm128_f16_2p(
    char* smem, int bn, int bm,
    const float* __restrict__ A,
    const __half* __restrict__ Bt_h,
    const __half* __restrict__ Bt_l,
    const float* __restrict__ bias,
    __half* __restrict__ Cout)
{
    const uint32_t sb = smem_u32(smem);
    const int tid   = threadIdx.x;
    const int lane  = tid & 31;
    const int wid   = tid >> 5;
    const int mwarp = wid & 1;
    const int nwarp = wid >> 1;
    const size_t rowBase = (size_t)bm * 128;

    float acc[4][4][4];
#pragma unroll
    for (int i = 0; i < 4; i++)
#pragma unroll
        for (int j = 0; j < 4; j++)
#pragma unroll
            for (int r = 0; r < 4; r++) acc[i][j][r] = 0.f;

    const int a_row = lane & 15, a_kh = lane >> 4;
    const uint32_t aAddr = sb + F_A +
        (uint32_t)(((mwarp * 64 + a_row) * SA + a_kh * 8) * 2);
    const int b_g = lane >> 3, b_r = lane & 7;
    const uint32_t bAddrBase = sb + F_B0 +
        (uint32_t)(((nwarp * 32 + (b_g >> 1) * 8 + b_r) * SA + (b_g & 1) * 8) * 2);

    // prologue: cp.async B(0)
#pragma unroll
    for (int it = 0; it < 4; it++) {
        int idx = tid + it * 256;
        int n = idx >> 3, q = idx & 7;
        uint32_t eoff = (uint32_t)((n * SA + q * 8) * 2);
        size_t goff = (size_t)(bn * 128 + n) * 256 + q * 8;
        CP_ASYNC16(sb + F_B0 + eoff,         Bt_h + goff);
        CP_ASYNC16(sb + F_B0 + 18432 + eoff, Bt_l + goff);
    }
    CP_COMMIT();

#pragma unroll 1
    for (int ch = 0; ch < 4; ch++) {
        const int buf = ch & 1;
        const int k0 = ch * 64;

        // A chunk -> single fp16 smem
#pragma unroll
        for (int it = 0; it < 8; it++) {
            int idx = tid + it * 256;
            int row = idx >> 4, q = idx & 15;
            float4 v = *(const float4*)(A + (rowBase + row) * 256 + k0 + q * 4);
            __half2 h01 = __floats2half2_rn(v.x, v.y);
            __half2 h23 = __floats2half2_rn(v.z, v.w);
            *(uint2*)(smem + F_A + (uint32_t)((row * SA + q * 4) * 2)) =
                make_uint2(*(uint32_t*)&h01, *(uint32_t*)&h23);
        }
        if (ch < 3) {
            const int k1 = k0 + 64;
            const uint32_t bsm = sb + F_B0 + (uint32_t)((buf ^ 1) * F_BSTRIDE);
#pragma unroll
            for (int it = 0; it < 4; it++) {
                int idx = tid + it * 256;
                int n = idx >> 3, q = idx & 7;
                uint32_t eoff = (uint32_t)((n * SA + q * 8) * 2);
                size_t goff = (size_t)(bn * 128 + n) * 256 + k1 + q * 8;
                CP_ASYNC16(bsm + eoff,         Bt_h + goff);
                CP_ASYNC16(bsm + 18432 + eoff, Bt_l + goff);
            }
            CP_COMMIT();
            CP_WAIT(1);
        } else {
            CP_WAIT(0);
        }
        __syncthreads();

        const uint32_t bAddrHi = bAddrBase + (uint32_t)(buf * F_BSTRIDE);
#pragma unroll
        for (int ks = 0; ks < 4; ks++) {
            const uint32_t kb = (uint32_t)(ks * 32);
            uint32_t ah[4][4];
#pragma unroll
            for (int mt = 0; mt < 4; mt++)
                ldsm_x4(ah[mt], aAddr + (uint32_t)(mt * 16 * SA * 2) + kb);
            uint32_t bh[2][4], bl[2][4];
#pragma unroll
            for (int pr = 0; pr < 2; pr++) {
                uint32_t bd = bAddrHi + (uint32_t)(pr * 16 * SA * 2) + kb;
                ldsm_x4(bh[pr], bd);
                ldsm_x4(bl[pr], bd + 18432);
            }
#pragma unroll
            for (int mt = 0; mt < 4; mt++)
#pragma unroll
                for (int nt = 0; nt < 4; nt++) {
                    const int pr = nt >> 1, h = (nt & 1) * 2;
                    mma_f16(acc[mt][nt], ah[mt], bh[pr][h], bh[pr][h + 1]);
                    mma_f16(acc[mt][nt], ah[mt], bl[pr][h], bl[pr][h + 1]);
                }
        }
        __syncthreads();
    }

#pragma unroll
    for (int nt = 0; nt < 4; nt++) {
        const int col = bn * 128 + nwarp * 32 + nt * 8 + (lane & 3) * 2;
        const float2 bb = *(const float2*)(bias + col);
#pragma unroll
        for (int mt = 0; mt < 4; mt++) {
            const size_t row0 = rowBase + mwarp * 64 + mt * 16 + (lane >> 2);
            __half2 h0 = __floats2half2_rn(acc[mt][nt][0] + bb.x,
                                           acc[mt][nt][1] + bb.y);
            __half2 h1 = __floats2half2_rn(acc[mt][nt][2] + bb.x,
                                           acc[mt][nt][3] + bb.y);
            *(__half2*)(Cout + row0 * 256 + col)       = h0;
            *(__half2*)(Cout + (row0 + 8) * 256 + col) = h1;
        }
    }
}

// ---- fat kernel: value GEMM (2-product fp16) + off/attn GEMM (3-product) --
__global__ __launch_bounds__(256, 2) void fused_gemms_kernel(
    const float* __restrict__ inp,
    const float* __restrict__ query,
    const float* __restrict__ bv)
{
    extern __shared__ char smem[];
    const int b = blockIdx.x;
    if (b < NVBLK) {
        gemm128_f16_2p(smem, b & 1, b >> 1, inp, g_wv_h, g_wv_l, bv, g_value);
    } else {
        const int c = b - NVBLK;
        gemm128_pipe<false>(smem, c & 3, c >> 2, query, g_wfa_hi, g_wfa_lo,
                            g_bfa, g_offattn, 512);
    }
}

// out-projection kernel (float out), 2-way N split
__global__ __launch_bounds__(256, 2) void out_gemm_kernel(
    const float* __restrict__ bias, float* __restrict__ out)
{
    extern __shared__ char smem[];
    const int b = blockIdx.x;
    gemm128_pipe<false>(smem, b & 1, b >> 1, g_mid, g_wo_hi, g_wo_lo,
                        bias, out, 256);
}

// ---- unified prep ----------------------------------------------------------
__global__ void prep_all_kernel(const float* __restrict__ Wv,
                                const float* __restrict__ Wout,
                                const float* __restrict__ Woff,
                                const float* __restrict__ Wattn,
                                const float* __restrict__ boff,
                                const float* __restrict__ battn)
{
    int idx = blockIdx.x * 256 + threadIdx.x;
    int row = idx >> 8, k = idx & 255;
    if (row < 256) {
        // Wv -> fp16 hi/lo split
        int n = row;
        float v = Wv[k * 256 + n];
        __half h = __float2half_rn(v);
        g_wv_h[n * 256 + k] = h;
        g_wv_l[n * 256 + k] = __float2half_rn(v - __half2float(h));
    } else {
        float v;
        __nv_bfloat16 *dh, *dl;
        int n;
        if (row < 512)      { n = row - 256; v = Wout[k * 256 + n]; dh = g_wo_hi;  dl = g_wo_lo;  }
        else if (row < 896) { n = row - 512; v = Woff[k * 384 + n]; dh = g_wfa_hi; dl = g_wfa_lo; }
        else                { n = row - 896 + 384;
                              v = Wattn[k * 128 + (row - 896)];     dh = g_wfa_hi; dl = g_wfa_lo; }
        __nv_bfloat16 h = __float2bfloat16(v);
        dh[n * 256 + k] = h;
        dl[n * 256 + k] = __float2bfloat16(v - __bfloat162float(h));
    }

    if (blockIdx.x < 2) {
        int t = blockIdx.x * 256 + threadIdx.x;
        g_bfa[t] = (t < 384) ? boff[t] : battn[t - 384];
    }
}

// ====== fused softmax + trilinear deformable sampling (fp16 value) =========
__global__ __launch_bounds__(256) void sample_kernel(
    const float* __restrict__ rp,
    const int*   __restrict__ shapes,
    const int*   __restrict__ starts)
{
    const int q    = blockIdx.x;
    const int h    = threadIdx.x >> 5;
    const int lane = threadIdx.x & 31;

    __shared__ float s_rp[NLEV * 3];
    __shared__ int   s_dim[NLEV * 3];
    __shared__ int   s_start[NLEV];
    __shared__ int2  s_pair[NHEADS][128];
    if (threadIdx.x < NLEV * 3) {
        s_rp[threadIdx.x]  = rp[(size_t)q * (NLEV * 3) + threadIdx.x];
        s_dim[threadIdx.x] = shapes[threadIdx.x];
    }
    if (threadIdx.x < NLEV) s_start[threadIdx.x] = starts[threadIdx.x];
    __syncthreads();

    const int n = q / LQ;
    const int o     = lane & 15;
    const int chalf = lane >> 4;
    const int l     = o >> 2;

    float logit = g_offattn[(size_t)q * 512 + 384 + h * 16 + o];
    float m = logit;
#pragma unroll
    for (int s = 8; s > 0; s >>= 1)
        m = fmaxf(m, __shfl_xor_sync(0xffffffffu, m, s, 16));
    float e = __expf(logit - m);
    float ssum = e;
#pragma unroll
    for (int s = 8; s > 0; s >>= 1)
        ssum += __shfl_xor_sync(0xffffffffu, ssum, s, 16);
    const float a = e / ssum;

    const float* offq = g_offattn + (size_t)q * 512 + h * 48 + o * 3;
    const int D = s_dim[l * 3 + 0];
    const int H = s_dim[l * 3 + 1];
    const int W = s_dim[l * 3 + 2];
    const float x = (s_rp[l * 3 + 0] + offq[0] / (float)W) * (float)W - 0.5f;
    const float y = (s_rp[l * 3 + 1] + offq[1] / (float)H) * (float)H - 0.5f;
    const float z = (s_rp[l * 3 + 2] + offq[2] / (float)D) * (float)D - 0.5f;
    const float x0f = floorf(x), y0f = floorf(y), z0f = floorf(z);
    const int   x0 = (int)x0f,   y0 = (int)y0f,   z0 = (int)z0f;
    const float fx = x - x0f,    fy = y - y0f,    fz = z - z0f;

#pragma unroll
    for (int cc = 0; cc < 4; cc++) {
        const int c  = chalf * 4 + cc;
        const int dx = c & 1, dy = (c >> 1) & 1, dz = (c >> 2) & 1;
        const int xi = x0 + dx, yi = y0 + dy, zi = z0 + dz;
        const float w = (dx ? fx : 1.f - fx)
                      * (dy ? fy : 1.f - fy)
                      * (dz ? fz : 1.f - fz);
        const bool valid = (xi >= 0) & (xi < W) & (yi >= 0) & (yi < H) &
                           (zi >= 0) & (zi < D);
        const int idxc = valid ? ((zi * H + yi) * W + xi) : 0;
        s_pair[h][o * 8 + c] =
            make_int2(idxc, __float_as_int(valid ? a * w : 0.f));
    }
    __syncwarp();

    const int g   = lane >> 3;
    const int ch4 = lane & 7;

    const int2* ph = s_pair[h];
    float a0 = 0.f, a1 = 0.f, a2 = 0.f, a3 = 0.f;

#pragma unroll
    for (int lv = 0; lv < NLEV; lv++) {
        const __half* vbl = g_value
            + ((size_t)(n * LEN_IN + s_start[lv])) * DM
            + h * DHEAD + ch4 * 4;
#pragma unroll
        for (int i8 = 0; i8 < 8; i8++) {
            const int i = lv * 8 + i8;
            int2 pk = ph[i * 4 + g];
            uint2 raw = __ldg((const uint2*)(vbl + (size_t)pk.x * DM));
            const float aw = __int_as_float(pk.y);
            float2 f0 = __half22float2(*(__half2*)&raw.x);
            float2 f1 = __half22float2(*(__half2*)&raw.y);
            a0 = fmaf(aw, f0.x, a0);
            a1 = fmaf(aw, f0.y, a1);
            a2 = fmaf(aw, f1.x, a2);
            a3 = fmaf(aw, f1.y, a3);
        }
    }

#pragma unroll
    for (int s = 8; s <= 16; s <<= 1) {
        a0 += __shfl_xor_sync(0xffffffffu, a0, s);
        a1 += __shfl_xor_sync(0xffffffffu, a1, s);
        a2 += __shfl_xor_sync(0xffffffffu, a2, s);
        a3 += __shfl_xor_sync(0xffffffffu, a3, s);
    }
    if (lane < 8) {
        float4 o4 = make_float4(a0, a1, a2, a3);
        *(float4*)(g_mid + (size_t)q * DM + h * DHEAD + ch4 * 4) = o4;
    }
}

// ---------------------------------------------------------------------------
extern "C" void kernel_launch(void* const* d_in, const int* in_sizes, int n_in,
                              void* d_out, int out_size)
{
    const float* query  = (const float*)d_in[0];
    const float* refp   = (const float*)d_in[1];
    const float* inp    = (const float*)d_in[2];
    const int*   shapes = (const int*)  d_in[3];
    const int*   starts = (const int*)  d_in[4];
    const float* Wv     = (const float*)d_in[5];
    const float* bv     = (const float*)d_in[6];
    const float* Woff   = (const float*)d_in[7];
    const float* boff   = (const float*)d_in[8];
    const float* Wattn  = (const float*)d_in[9];
    const float* battn  = (const float*)d_in[10];
    const float* Wout   = (const float*)d_in[11];
    const float* bout   = (const float*)d_in[12];
    float* out = (float*)d_out;

    cudaFuncSetAttribute(fused_gemms_kernel,
                         cudaFuncAttributeMaxDynamicSharedMemorySize, SMEM_P);
    cudaFuncSetAttribute(out_gemm_kernel,
                         cudaFuncAttributeMaxDynamicSharedMemorySize, SMEM_P);

    // 0) prep weight splits + fused off/attn bias
    prep_all_kernel<<<1024, 256>>>(Wv, Wout, Woff, Wattn, boff, battn);

    // 1) fused: value GEMM (fp16 2-product) + [off|attn] GEMM (bf16 3-product)
    fused_gemms_kernel<<<NVBLK + 512, 256, SMEM_P>>>(inp, query, bv);

    // 2) fused softmax + deformable trilinear sampling -> g_mid
    sample_kernel<<<NB * LQ, 256>>>(refp, shapes, starts);

    // 3) out = g_mid @ Wout + bout  (N-split 2)
    out_gemm_kernel<<<(NB * LQ) / 128 * 2, 256, SMEM_P>>>(bout, out);
}

// round 16
// speedup vs baseline: 1.5200x; 1.0236x over previous
#include <cuda_runtime.h>
#include <cuda_fp16.h>
#include <math.h>
#include <stdint.h>

#define NB      2
#define LQ      8192
#define LEN_IN  149760
#define DM      256
#define NHEADS  8
#define NLEV    4
#define NPTS    4
#define DHEAD   32
#define NVBLK   (((NB * LEN_IN) / 128) * 2)   // 4680 value blocks (N-split 2)

// ---------------- scratch (device globals; no cudaMalloc allowed) ----------
__device__ __half g_value[(size_t)NB * LEN_IN * DM];                     // 153 MB
__device__ float  g_offattn[(size_t)NB * LQ * 512];                     // off 0..383, logits 384..511
__device__ __half g_mid  [(size_t)NB * LQ * DM];                        // 8 MB (fp16)
__device__ __half g_wv_h [DM * DM];        // Wv^T   fp16 hi
__device__ __half g_wv_l [DM * DM];        //        fp16 lo
__device__ __half g_wo_h [DM * DM];        // Wout^T fp16 hi/lo
__device__ __half g_wo_l [DM * DM];
__device__ __half g_wfa_h[512 * DM];       // [Woff|Wattn]^T fp16 hi/lo
__device__ __half g_wfa_l[512 * DM];
__device__ float  g_bfa[512];

// ============================ PTX helpers ===================================
__device__ __forceinline__ uint32_t smem_u32(const void* p) {
    uint32_t a;
    asm("{ .reg .u64 t; cvta.to.shared.u64 t, %1; cvt.u32.u64 %0, t; }" : "=r"(a) : "l"(p));
    return a;
}
__device__ __forceinline__ void ldsm_x4(uint32_t* r, uint32_t addr) {
    asm volatile("ldmatrix.sync.aligned.m8n8.x4.shared.b16 {%0,%1,%2,%3}, [%4];"
        : "=r"(r[0]), "=r"(r[1]), "=r"(r[2]), "=r"(r[3]) : "r"(addr));
}
__device__ __forceinline__ void mma_f16(float* d, const uint32_t* a,
                                        uint32_t b0, uint32_t b1) {
    asm volatile(
        "mma.sync.aligned.m16n8k16.row.col.f32.f16.f16.f32 "
        "{%0,%1,%2,%3}, {%4,%5,%6,%7}, {%8,%9}, {%0,%1,%2,%3};"
        : "+f"(d[0]), "+f"(d[1]), "+f"(d[2]), "+f"(d[3])
        : "r"(a[0]), "r"(a[1]), "r"(a[2]), "r"(a[3]), "r"(b0), "r"(b1));
}
#define CP_ASYNC16(dst, src) \
    asm volatile("cp.async.cg.shared.global [%0], [%1], 16;" :: "r"(dst), "l"(src))
#define CP_COMMIT() asm volatile("cp.async.commit_group;" ::: "memory")
#define CP_WAIT(n)  asm volatile("cp.async.wait_group %0;" :: "n"(n) : "memory")

#define SA        72

// ======== 2-product fp16 GEMM, A fp32 in global (value / offattn) ==========
// SMEM: A fp16 (18KB at 0); B fp16 hi+lo double-buffered at 18432 (+36864/buf)
#define F_A       0
#define F_B0      18432
#define F_BSTRIDE 36864
#define SMEM_P    110592

template <bool HALF_OUT>
__device__ __forceinline__ void gemm128_f16_2p(
    char* smem, int bn, int bm,
    const float* __restrict__ A,
    const __half* __restrict__ Bt_h,
    const __half* __restrict__ Bt_l,
    const float* __restrict__ bias,
    void* __restrict__ Cout, int Nc)
{
    const uint32_t sb = smem_u32(smem);
    const int tid   = threadIdx.x;
    const int lane  = tid & 31;
    const int wid   = tid >> 5;
    const int mwarp = wid & 1;
    const int nwarp = wid >> 1;
    const size_t rowBase = (size_t)bm * 128;

    float acc[4][4][4];
#pragma unroll
    for (int i = 0; i < 4; i++)
#pragma unroll
        for (int j = 0; j < 4; j++)
#pragma unroll
            for (int r = 0; r < 4; r++) acc[i][j][r] = 0.f;

    const int a_row = lane & 15, a_kh = lane >> 4;
    const uint32_t aAddr = sb + F_A +
        (uint32_t)(((mwarp * 64 + a_row) * SA + a_kh * 8) * 2);
    const int b_g = lane >> 3, b_r = lane & 7;
    const uint32_t bAddrBase = sb + F_B0 +
        (uint32_t)(((nwarp * 32 + (b_g >> 1) * 8 + b_r) * SA + (b_g & 1) * 8) * 2);

    // prologue: cp.async B(0)
#pragma unroll
    for (int it = 0; it < 4; it++) {
        int idx = tid + it * 256;
        int n = idx >> 3, q = idx & 7;
        uint32_t eoff = (uint32_t)((n * SA + q * 8) * 2);
        size_t goff = (size_t)(bn * 128 + n) * 256 + q * 8;
        CP_ASYNC16(sb + F_B0 + eoff,         Bt_h + goff);
        CP_ASYNC16(sb + F_B0 + 18432 + eoff, Bt_l + goff);
    }
    CP_COMMIT();

#pragma unroll 1
    for (int ch = 0; ch < 4; ch++) {
        const int buf = ch & 1;
        const int k0 = ch * 64;

        // A chunk -> single fp16 smem
#pragma unroll
        for (int it = 0; it < 8; it++) {
            int idx = tid + it * 256;
            int row = idx >> 4, q = idx & 15;
            float4 v = *(const float4*)(A + (rowBase + row) * 256 + k0 + q * 4);
            __half2 h01 = __floats2half2_rn(v.x, v.y);
            __half2 h23 = __floats2half2_rn(v.z, v.w);
            *(uint2*)(smem + F_A + (uint32_t)((row * SA + q * 4) * 2)) =
                make_uint2(*(uint32_t*)&h01, *(uint32_t*)&h23);
        }
        if (ch < 3) {
            const int k1 = k0 + 64;
            const uint32_t bsm = sb + F_B0 + (uint32_t)((buf ^ 1) * F_BSTRIDE);
#pragma unroll
            for (int it = 0; it < 4; it++) {
                int idx = tid + it * 256;
                int n = idx >> 3, q = idx & 7;
                uint32_t eoff = (uint32_t)((n * SA + q * 8) * 2);
                size_t goff = (size_t)(bn * 128 + n) * 256 + k1 + q * 8;
                CP_ASYNC16(bsm + eoff,         Bt_h + goff);
                CP_ASYNC16(bsm + 18432 + eoff, Bt_l + goff);
            }
            CP_COMMIT();
            CP_WAIT(1);
        } else {
            CP_WAIT(0);
        }
        __syncthreads();

        const uint32_t bAddrHi = bAddrBase + (uint32_t)(buf * F_BSTRIDE);
#pragma unroll
        for (int ks = 0; ks < 4; ks++) {
            const uint32_t kb = (uint32_t)(ks * 32);
            uint32_t ah[4][4];
#pragma unroll
            for (int mt = 0; mt < 4; mt++)
                ldsm_x4(ah[mt], aAddr + (uint32_t)(mt * 16 * SA * 2) + kb);
            uint32_t bh[2][4], bl[2][4];
#pragma unroll
            for (int pr = 0; pr < 2; pr++) {
                uint32_t bd = bAddrHi + (uint32_t)(pr * 16 * SA * 2) + kb;
                ldsm_x4(bh[pr], bd);
                ldsm_x4(bl[pr], bd + 18432);
            }
#pragma unroll
            for (int mt = 0; mt < 4; mt++)
#pragma unroll
                for (int nt = 0; nt < 4; nt++) {
                    const int pr = nt >> 1, h = (nt & 1) * 2;
                    mma_f16(acc[mt][nt], ah[mt], bh[pr][h], bh[pr][h + 1]);
                    mma_f16(acc[mt][nt], ah[mt], bl[pr][h], bl[pr][h + 1]);
                }
        }
        __syncthreads();
    }

#pragma unroll
    for (int nt = 0; nt < 4; nt++) {
        const int col = bn * 128 + nwarp * 32 + nt * 8 + (lane & 3) * 2;
        const float2 bb = *(const float2*)(bias + col);
#pragma unroll
        for (int mt = 0; mt < 4; mt++) {
            const size_t row0 = rowBase + mwarp * 64 + mt * 16 + (lane >> 2);
            if (HALF_OUT) {
                __half* Ch = (__half*)Cout;
                __half2 h0 = __floats2half2_rn(acc[mt][nt][0] + bb.x,
                                               acc[mt][nt][1] + bb.y);
                __half2 h1 = __floats2half2_rn(acc[mt][nt][2] + bb.x,
                                               acc[mt][nt][3] + bb.y);
                *(__half2*)(Ch + row0 * Nc + col)       = h0;
                *(__half2*)(Ch + (row0 + 8) * Nc + col) = h1;
            } else {
                float* Cf = (float*)Cout;
                float2 o0, o1;
                o0.x = acc[mt][nt][0] + bb.x; o0.y = acc[mt][nt][1] + bb.y;
                o1.x = acc[mt][nt][2] + bb.x; o1.y = acc[mt][nt][3] + bb.y;
                *(float2*)(Cf + row0 * Nc + col)       = o0;
                *(float2*)(Cf + (row0 + 8) * Nc + col) = o1;
            }
        }
    }
}

// ======== 2-product fp16 GEMM, A fp16 in global (out projection) ===========
// Fully cp.async: A double-buffered at 0/18432, B(hi,lo) at 36864+buf*36864.
__device__ __forceinline__ void gemm128_h16(
    char* smem, int bn, int bm,
    const __half* __restrict__ A,
    const __half* __restrict__ Bt_h,
    const __half* __restrict__ Bt_l,
    const float* __restrict__ bias,
    float* __restrict__ Cout)
{
    const uint32_t sb = smem_u32(smem);
    const int tid   = threadIdx.x;
    const int lane  = tid & 31;
    const int wid   = tid >> 5;
    const int mwarp = wid & 1;
    const int nwarp = wid >> 1;
    const size_t rowBase = (size_t)bm * 128;

    float acc[4][4][4];
#pragma unroll
    for (int i = 0; i < 4; i++)
#pragma unroll
        for (int j = 0; j < 4; j++)
#pragma unroll
            for (int r = 0; r < 4; r++) acc[i][j][r] = 0.f;

    const int a_row = lane & 15, a_kh = lane >> 4;
    const uint32_t aAddrBase = sb +
        (uint32_t)(((mwarp * 64 + a_row) * SA + a_kh * 8) * 2);
    const int b_g = lane >> 3, b_r = lane & 7;
    const uint32_t bAddrBase = sb + 36864 +
        (uint32_t)(((nwarp * 32 + (b_g >> 1) * 8 + b_r) * SA + (b_g & 1) * 8) * 2);

    // prologue: cp.async A(0) + B(0)
#pragma unroll
    for (int it = 0; it < 4; it++) {
        int idx = tid + it * 256;
        int r = idx >> 3, q = idx & 7;
        uint32_t eoff = (uint32_t)((r * SA + q * 8) * 2);
        CP_ASYNC16(sb + eoff, A + (rowBase + r) * 256 + q * 8);
        size_t goff = (size_t)(bn * 128 + r) * 256 + q * 8;
        CP_ASYNC16(sb + 36864 + eoff,         Bt_h + goff);
        CP_ASYNC16(sb + 36864 + 18432 + eoff, Bt_l + goff);
    }
    CP_COMMIT();

#pragma unroll 1
    for (int ch = 0; ch < 4; ch++) {
        const int buf = ch & 1;
        if (ch < 3) {
            const int k1 = (ch + 1) * 64;
            const uint32_t asm_ = sb + (uint32_t)((buf ^ 1) * 18432);
            const uint32_t bsm  = sb + 36864 + (uint32_t)((buf ^ 1) * F_BSTRIDE);
#pragma unroll
            for (int it = 0; it < 4; it++) {
                int idx = tid + it * 256;
                int r = idx >> 3, q = idx & 7;
                uint32_t eoff = (uint32_t)((r * SA + q * 8) * 2);
                CP_ASYNC16(asm_ + eoff, A + (rowBase + r) * 256 + k1 + q * 8);
                size_t goff = (size_t)(bn * 128 + r) * 256 + k1 + q * 8;
                CP_ASYNC16(bsm + eoff,         Bt_h + goff);
                CP_ASYNC16(bsm + 18432 + eoff, Bt_l + goff);
            }
            CP_COMMIT();
            CP_WAIT(1);
        } else {
            CP_WAIT(0);
        }
        __syncthreads();

        const uint32_t aAddr   = aAddrBase + (uint32_t)(buf * 18432);
        const uint32_t bAddrHi = bAddrBase + (uint32_t)(buf * F_BSTRIDE);
#pragma unroll
        for (int ks = 0; ks < 4; ks++) {
            const uint32_t kb = (uint32_t)(ks * 32);
            uint32_t ah[4][4];
#pragma unroll
            for (int mt = 0; mt < 4; mt++)
                ldsm_x4(ah[mt], aAddr + (uint32_t)(mt * 16 * SA * 2) + kb);
            uint32_t bh[2][4], bl[2][4];
#pragma unroll
            for (int pr = 0; pr < 2; pr++) {
                uint32_t bd = bAddrHi + (uint32_t)(pr * 16 * SA * 2) + kb;
                ldsm_x4(bh[pr], bd);
                ldsm_x4(bl[pr], bd + 18432);
            }
#pragma unroll
            for (int mt = 0; mt < 4; mt++)
#pragma unroll
                for (int nt = 0; nt < 4; nt++) {
                    const int pr = nt >> 1, h = (nt & 1) * 2;
                    mma_f16(acc[mt][nt], ah[mt], bh[pr][h], bh[pr][h + 1]);
                    mma_f16(acc[mt][nt], ah[mt], bl[pr][h], bl[pr][h + 1]);
                }
        }
        __syncthreads();
    }

#pragma unroll
    for (int nt = 0; nt < 4; nt++) {
        const int col = bn * 128 + nwarp * 32 + nt * 8 + (lane & 3) * 2;
        const float2 bb = *(const float2*)(bias + col);
#pragma unroll
        for (int mt = 0; mt < 4; mt++) {
            const size_t row0 = rowBase + mwarp * 64 + mt * 16 + (lane >> 2);
            float2 o0, o1;
            o0.x = acc[mt][nt][0] + bb.x; o0.y = acc[mt][nt][1] + bb.y;
            o1.x = acc[mt][nt][2] + bb.x; o1.y = acc[mt][nt][3] + bb.y;
            *(float2*)(Cout + row0 * 256 + col)       = o0;
            *(float2*)(Cout + (row0 + 8) * 256 + col) = o1;
        }
    }
}

// ---- fat kernel: value GEMM + off/attn GEMM (both fp16 2-product) ---------
__global__ __launch_bounds__(256, 2) void fused_gemms_kernel(
    const float* __restrict__ inp,
    const float* __restrict__ query,
    const float* __restrict__ bv)
{
    extern __shared__ char smem[];
    const int b = blockIdx.x;
    if (b < NVBLK) {
        gemm128_f16_2p<true>(smem, b & 1, b >> 1, inp, g_wv_h, g_wv_l,
                             bv, g_value, 256);
    } else {
        const int c = b - NVBLK;
        gemm128_f16_2p<false>(smem, c & 3, c >> 2, query, g_wfa_h, g_wfa_l,
                              g_bfa, g_offattn, 512);
    }
}

// out-projection kernel (fp16 A, float out), 2-way N split
__global__ __launch_bounds__(256, 2) void out_gemm_kernel(
    const float* __restrict__ bias, float* __restrict__ out)
{
    extern __shared__ char smem[];
    const int b = blockIdx.x;
    gemm128_h16(smem, b & 1, b >> 1, g_mid, g_wo_h, g_wo_l, bias, out);
}

// ---- unified prep: fp16 hi/lo splits of all weights + fused bias ----------
__global__ void prep_all_kernel(const float* __restrict__ Wv,
                                const float* __restrict__ Wout,
                                const float* __restrict__ Woff,
                                const float* __restrict__ Wattn,
                                const float* __restrict__ boff,
                                const float* __restrict__ battn)
{
    int idx = blockIdx.x * 256 + threadIdx.x;
    int row = idx >> 8, k = idx & 255;
    float v;
    __half *dh, *dl;
    int n;
    if (row < 256)      { n = row;       v = Wv  [k * 256 + n]; dh = g_wv_h;  dl = g_wv_l;  }
    else if (row < 512) { n = row - 256; v = Wout[k * 256 + n]; dh = g_wo_h;  dl = g_wo_l;  }
    else if (row < 896) { n = row - 512; v = Woff[k * 384 + n]; dh = g_wfa_h; dl = g_wfa_l; }
    else                { n = row - 896 + 384;
                          v = Wattn[k * 128 + (row - 896)];     dh = g_wfa_h; dl = g_wfa_l; }
    __half h = __float2half_rn(v);
    dh[n * 256 + k] = h;
    dl[n * 256 + k] = __float2half_rn(v - __half2float(h));

    if (blockIdx.x < 2) {
        int t = blockIdx.x * 256 + threadIdx.x;
        g_bfa[t] = (t < 384) ? boff[t] : battn[t - 384];
    }
}

// ====== fused softmax + trilinear deformable sampling (fp16 value/mid) =====
__global__ __launch_bounds__(256) void sample_kernel(
    const float* __restrict__ rp,
    const int*   __restrict__ shapes,
    const int*   __restrict__ starts)
{
    const int q    = blockIdx.x;
    const int h    = threadIdx.x >> 5;
    const int lane = threadIdx.x & 31;

    __shared__ float s_rp[NLEV * 3];
    __shared__ int   s_dim[NLEV * 3];
    __shared__ int   s_start[NLEV];
    __shared__ int2  s_pair[NHEADS][128];
    if (threadIdx.x < NLEV * 3) {
        s_rp[threadIdx.x]  = rp[(size_t)q * (NLEV * 3) + threadIdx.x];
        s_dim[threadIdx.x] = shapes[threadIdx.x];
    }
    if (threadIdx.x < NLEV) s_start[threadIdx.x] = starts[threadIdx.x];
    __syncthreads();

    const int n = q / LQ;
    const int o     = lane & 15;
    const int chalf = lane >> 4;
    const int l     = o >> 2;

    float logit = g_offattn[(size_t)q * 512 + 384 + h * 16 + o];
    float m = logit;
#pragma unroll
    for (int s = 8; s > 0; s >>= 1)
        m = fmaxf(m, __shfl_xor_sync(0xffffffffu, m, s, 16));
    float e = __expf(logit - m);
    float ssum = e;
#pragma unroll
    for (int s = 8; s > 0; s >>= 1)
        ssum += __shfl_xor_sync(0xffffffffu, ssum, s, 16);
    const float a = e / ssum;

    const float* offq = g_offattn + (size_t)q * 512 + h * 48 + o * 3;
    const int D = s_dim[l * 3 + 0];
    const int H = s_dim[l * 3 + 1];
    const int W = s_dim[l * 3 + 2];
    const float x = (s_rp[l * 3 + 0] + offq[0] / (float)W) * (float)W - 0.5f;
    const float y = (s_rp[l * 3 + 1] + offq[1] / (float)H) * (float)H - 0.5f;
    const float z = (s_rp[l * 3 + 2] + offq[2] / (float)D) * (float)D - 0.5f;
    const float x0f = floorf(x), y0f = floorf(y), z0f = floorf(z);
    const int   x0 = (int)x0f,   y0 = (int)y0f,   z0 = (int)z0f;
    const float fx = x - x0f,    fy = y - y0f,    fz = z - z0f;

#pragma unroll
    for (int cc = 0; cc < 4; cc++) {
        const int c  = chalf * 4 + cc;
        const int dx = c & 1, dy = (c >> 1) & 1, dz = (c >> 2) & 1;
        const int xi = x0 + dx, yi = y0 + dy, zi = z0 + dz;
        const float w = (dx ? fx : 1.f - fx)
                      * (dy ? fy : 1.f - fy)
                      * (dz ? fz : 1.f - fz);
        const bool valid = (xi >= 0) & (xi < W) & (yi >= 0) & (yi < H) &
                           (zi >= 0) & (zi < D);
        const int idxc = valid ? ((zi * H + yi) * W + xi) : 0;
        s_pair[h][o * 8 + c] =
            make_int2(idxc, __float_as_int(valid ? a * w : 0.f));
    }
    __syncwarp();

    const int g   = lane >> 3;
    const int ch4 = lane & 7;

    const int2* ph = s_pair[h];
    float a0 = 0.f, a1 = 0.f, a2 = 0.f, a3 = 0.f;

#pragma unroll
    for (int lv = 0; lv < NLEV; lv++) {
        const __half* vbl = g_value
            + ((size_t)(n * LEN_IN + s_start[lv])) * DM
            + h * DHEAD + ch4 * 4;
#pragma unroll
        for (int i8 = 0; i8 < 8; i8++) {
            const int i = lv * 8 + i8;
            int2 pk = ph[i * 4 + g];
            uint2 raw = __ldg((const uint2*)(vbl + (size_t)pk.x * DM));
            const float aw = __int_as_float(pk.y);
            float2 f0 = __half22float2(*(__half2*)&raw.x);
            float2 f1 = __half22float2(*(__half2*)&raw.y);
            a0 = fmaf(aw, f0.x, a0);
            a1 = fmaf(aw, f0.y, a1);
            a2 = fmaf(aw, f1.x, a2);
            a3 = fmaf(aw, f1.y, a3);
        }
    }

#pragma unroll
    for (int s = 8; s <= 16; s <<= 1) {
        a0 += __shfl_xor_sync(0xffffffffu, a0, s);
        a1 += __shfl_xor_sync(0xffffffffu, a1, s);
        a2 += __shfl_xor_sync(0xffffffffu, a2, s);
        a3 += __shfl_xor_sync(0xffffffffu, a3, s);
    }
    if (lane < 8) {
        __half2 h0 = __floats2half2_rn(a0, a1);
        __half2 h1 = __floats2half2_rn(a2, a3);
        *(uint2*)(g_mid + (size_t)q * DM + h * DHEAD + ch4 * 4) =
            make_uint2(*(uint32_t*)&h0, *(uint32_t*)&h1);
    }
}

// ---------------------------------------------------------------------------
extern "C" void kernel_launch(void* const* d_in, const int* in_sizes, int n_in,
                              void* d_out, int out_size)
{
    const float* query  = (const float*)d_in[0];
    const float* refp   = (const float*)d_in[1];
    const float* inp    = (const float*)d_in[2];
    const int*   shapes = (const int*)  d_in[3];
    const int*   starts = (const int*)  d_in[4];
    const float* Wv     = (const float*)d_in[5];
    const float* bv     = (const float*)d_in[6];
    const float* Woff   = (const float*)d_in[7];
    const float* boff   = (const float*)d_in[8];
    const float* Wattn  = (const float*)d_in[9];
    const float* battn  = (const float*)d_in[10];
    const float* Wout   = (const float*)d_in[11];
    const float* bout   = (const float*)d_in[12];
    float* out = (float*)d_out;

    cudaFuncSetAttribute(fused_gemms_kernel,
                         cudaFuncAttributeMaxDynamicSharedMemorySize, SMEM_P);
    cudaFuncSetAttribute(out_gemm_kernel,
                         cudaFuncAttributeMaxDynamicSharedMemorySize, SMEM_P);

    // 0) prep fp16 weight splits + fused off/attn bias
    prep_all_kernel<<<1024, 256>>>(Wv, Wout, Woff, Wattn, boff, battn);

    // 1) fused: value GEMM + [off|attn] GEMM (fp16 2-product)
    fused_gemms_kernel<<<NVBLK + 512, 256, SMEM_P>>>(inp, query, bv);

    // 2) fused softmax + deformable trilinear sampling -> g_mid (fp16)
    sample_kernel<<<NB * LQ, 256>>>(refp, shapes, starts);

    // 3) out = g_mid @ Wout + bout  (fp16 A, fully cp.async pipelined)
    out_gemm_kernel<<<(NB * LQ) / 128 * 2, 256, SMEM_P>>>(bout, out);
}